// round 2
// baseline (speedup 1.0000x reference)
#include <cuda_runtime.h>
#include <math.h>

#define MTOT 32768
#define DD   1024
#define RR   32

// ---------------- device scratch (no allocations allowed) ----------------
__device__ float g_W[6 * 1024 * 1024];   // dequantized weights [layer][out][in]
__device__ float g_H[MTOT * DD];         // hidden state h
__device__ float g_Y[MTOT * DD];         // intermediate y
__device__ float g_U[MTOT * RR];         // LoRA intermediate u = x @ la^T

// ---------------- dequant: w = (q/7.5 - 1) * scale[group] ----------------
__global__ void k_dequant(const int* __restrict__ q, const float* __restrict__ s) {
    int idx = blockIdx.x * 256 + threadIdx.x;      // over 6*1024*1024
    int in  = idx & 1023;
    int row = idx >> 10;                           // l*1024 + o
    float w = (float)q[idx] * (1.0f / 7.5f) - 1.0f;
    g_W[idx] = w * s[row * 64 + (in >> 4)];
}

__global__ void k_copy(const float4* __restrict__ src, float4* __restrict__ dst, int n4) {
    int i = blockIdx.x * 256 + threadIdx.x;
    if (i < n4) dst[i] = src[i];
}

// ---------------- LoRA-A: U[t,r] = sum_k A[t,k] * la[r,k] ----------------
// BM=128 tokens, N=32 (full), BK=32, 128 threads, thread tile 8x4
__global__ void __launch_bounds__(128) k_loraA(const float* __restrict__ A,
                                               const float* __restrict__ la,
                                               float* __restrict__ U) {
    __shared__ __align__(16) float As[32][132];
    __shared__ __align__(16) float Ls[32][36];
    int tid = threadIdx.x;
    int m0  = blockIdx.x * 128;
    int ty  = tid >> 3;   // 0..15 (m groups of 8)
    int tx  = tid & 7;    // 0..7  (r groups of 4)

    float acc[8][4] = {};
    float4 pa[8], pl[2];

    auto ldg = [&](int kt) {
        int k0 = kt * 32;
#pragma unroll
        for (int j = 0; j < 8; j++) {
            int idx = j * 128 + tid;              // 1024 float4s
            int row = idx >> 3, c = idx & 7;
            pa[j] = *(const float4*)(A + (m0 + row) * DD + k0 + c * 4);
        }
#pragma unroll
        for (int j = 0; j < 2; j++) {
            int idx = j * 128 + tid;              // 256 float4s
            int r = idx >> 3, kc = idx & 7;
            pl[j] = *(const float4*)(la + r * DD + k0 + kc * 4);
        }
    };
    auto sts = [&]() {
#pragma unroll
        for (int j = 0; j < 8; j++) {
            int idx = j * 128 + tid;
            int row = idx >> 3, c = idx & 7;
            As[c * 4 + 0][row] = pa[j].x; As[c * 4 + 1][row] = pa[j].y;
            As[c * 4 + 2][row] = pa[j].z; As[c * 4 + 3][row] = pa[j].w;
        }
#pragma unroll
        for (int j = 0; j < 2; j++) {
            int idx = j * 128 + tid;
            int r = idx >> 3, kc = idx & 7;
            Ls[kc * 4 + 0][r] = pl[j].x; Ls[kc * 4 + 1][r] = pl[j].y;
            Ls[kc * 4 + 2][r] = pl[j].z; Ls[kc * 4 + 3][r] = pl[j].w;
        }
    };

    ldg(0); sts(); __syncthreads();
    for (int kt = 0; kt < 32; ++kt) {
        if (kt + 1 < 32) ldg(kt + 1);
#pragma unroll
        for (int kk = 0; kk < 32; ++kk) {
            float a[8], b[4];
#pragma unroll
            for (int i = 0; i < 8; i++) a[i] = As[kk][ty * 8 + i];
#pragma unroll
            for (int j = 0; j < 4; j++) b[j] = Ls[kk][tx * 4 + j];
#pragma unroll
            for (int i = 0; i < 8; i++)
#pragma unroll
                for (int j = 0; j < 4; j++) acc[i][j] += a[i] * b[j];
        }
        __syncthreads();
        if (kt + 1 < 32) { sts(); __syncthreads(); }
    }
#pragma unroll
    for (int i = 0; i < 8; i++)
#pragma unroll
        for (int j = 0; j < 4; j++)
            U[(m0 + ty * 8 + i) * RR + tx * 4 + j] = acc[i][j];
}

// ---------------- main GEMM: C = A @ W^T + bias + U @ lb^T (+res) --------
// BM=128, BN=64, BK=16, 256 threads, thread tile 8x4, double-buffered smem
template <int MODE>  // 0: plain store, 1: add residual
__global__ void __launch_bounds__(256) k_gemm(const float* __restrict__ A,
                                              const float* __restrict__ W,
                                              const float* __restrict__ bias,
                                              const float* __restrict__ lb,
                                              const float* __restrict__ U,
                                              const float* res, float* C) {
    __shared__ __align__(16) float As[2][16][132];
    __shared__ __align__(16) float Bs[2][16][68];
    __shared__ __align__(16) float lbs[64][32];
    int tid = threadIdx.x;
    int n0  = blockIdx.x * 64;
    int m0  = blockIdx.y * 128;
    int ty  = tid >> 4;   // 0..15 (m)
    int tx  = tid & 15;   // 0..15 (n)

    // preload lb tile [64 outs][32 r]
#pragma unroll
    for (int j = 0; j < 2; j++) {
        int idx = j * 256 + tid;                  // 512 float4s
        int o = idx >> 3, rc = idx & 7;
        *(float4*)&lbs[o][rc * 4] = *(const float4*)(lb + (n0 + o) * RR + rc * 4);
    }

    float acc[8][4] = {};
    float4 pa[2], pb;

    auto ldg = [&](int kt) {
        int k0 = kt * 16;
#pragma unroll
        for (int j = 0; j < 2; j++) {
            int idx = j * 256 + tid;              // 512 float4s
            int row = idx >> 2, c = idx & 3;
            pa[j] = *(const float4*)(A + (m0 + row) * DD + k0 + c * 4);
        }
        {
            int row = tid >> 2, c = tid & 3;      // 256 float4s
            pb = *(const float4*)(W + (n0 + row) * DD + k0 + c * 4);
        }
    };
    auto sts = [&](int buf) {
#pragma unroll
        for (int j = 0; j < 2; j++) {
            int idx = j * 256 + tid;
            int row = idx >> 2, c = idx & 3;
            As[buf][c * 4 + 0][row] = pa[j].x; As[buf][c * 4 + 1][row] = pa[j].y;
            As[buf][c * 4 + 2][row] = pa[j].z; As[buf][c * 4 + 3][row] = pa[j].w;
        }
        {
            int row = tid >> 2, c = tid & 3;
            Bs[buf][c * 4 + 0][row] = pb.x; Bs[buf][c * 4 + 1][row] = pb.y;
            Bs[buf][c * 4 + 2][row] = pb.z; Bs[buf][c * 4 + 3][row] = pb.w;
        }
    };

    ldg(0); sts(0); __syncthreads();
    const int NKT = DD / 16;  // 64
    for (int kt = 0; kt < NKT; ++kt) {
        int cur = kt & 1;
        if (kt + 1 < NKT) ldg(kt + 1);
#pragma unroll
        for (int kk = 0; kk < 16; ++kk) {
            float4 a0 = *(const float4*)&As[cur][kk][ty * 8];
            float4 a1 = *(const float4*)&As[cur][kk][ty * 8 + 4];
            float4 b0 = *(const float4*)&Bs[cur][kk][tx * 4];
            float a[8] = {a0.x, a0.y, a0.z, a0.w, a1.x, a1.y, a1.z, a1.w};
            float b[4] = {b0.x, b0.y, b0.z, b0.w};
#pragma unroll
            for (int i = 0; i < 8; i++)
#pragma unroll
                for (int j = 0; j < 4; j++) acc[i][j] += a[i] * b[j];
        }
        if (kt + 1 < NKT) sts(cur ^ 1);
        __syncthreads();
    }

    // LoRA epilogue: stage U[128][32] into the (now free) As region
    float* Us = &As[0][0][0];                     // 4096 floats fit in 2*16*132
#pragma unroll
    for (int j = 0; j < 4; j++) {
        int idx = j * 256 + tid;                  // 1024 float4s
        int m = idx >> 3, rc = idx & 7;
        *(float4*)&Us[m * 32 + rc * 4] = *(const float4*)(U + (m0 + m) * RR + rc * 4);
    }
    __syncthreads();
#pragma unroll
    for (int r = 0; r < RR; ++r) {
        float bv[4];
#pragma unroll
        for (int j = 0; j < 4; j++) bv[j] = lbs[tx * 4 + j][r];
#pragma unroll
        for (int i = 0; i < 8; i++) {
            float uv = Us[(ty * 8 + i) * 32 + r];
#pragma unroll
            for (int j = 0; j < 4; j++) acc[i][j] += uv * bv[j];
        }
    }

    float bcol[4];
#pragma unroll
    for (int j = 0; j < 4; j++) bcol[j] = bias[n0 + tx * 4 + j];
#pragma unroll
    for (int i = 0; i < 8; i++) {
        int row = m0 + ty * 8 + i;
#pragma unroll
        for (int j = 0; j < 4; j++) {
            int col = n0 + tx * 4 + j;
            float v = acc[i][j] + bcol[j];
            if (MODE == 1) v += res[row * DD + col];
            C[row * DD + col] = v;
        }
    }
}

// ---------------- LayerNorm + exact GELU, warp per token -----------------
__global__ void __launch_bounds__(256) k_lngelu(float* Y, const float* __restrict__ g,
                                                const float* __restrict__ b) {
    int warp = threadIdx.x >> 5, lane = threadIdx.x & 31;
    int t = blockIdx.x * 8 + warp;
    const float4* row = (const float4*)(Y + t * DD);
    float4 v[8];
    float s = 0.f, sq = 0.f;
#pragma unroll
    for (int i = 0; i < 8; i++) {
        v[i] = row[i * 32 + lane];
        s  += v[i].x + v[i].y + v[i].z + v[i].w;
        sq += v[i].x * v[i].x + v[i].y * v[i].y + v[i].z * v[i].z + v[i].w * v[i].w;
    }
#pragma unroll
    for (int o = 16; o > 0; o >>= 1) {
        s  += __shfl_xor_sync(0xffffffffu, s, o);
        sq += __shfl_xor_sync(0xffffffffu, sq, o);
    }
    float mu  = s * (1.f / 1024.f);
    float var = sq * (1.f / 1024.f) - mu * mu;
    float rs  = rsqrtf(var + 1e-5f);
    float4* wrow = (float4*)(Y + t * DD);
#pragma unroll
    for (int i = 0; i < 8; i++) {
        int c4 = (i * 32 + lane) * 4;
        float x[4] = {v[i].x, v[i].y, v[i].z, v[i].w};
        float4 o4;
        float* po = &o4.x;
#pragma unroll
        for (int j = 0; j < 4; j++) {
            float xn = (x[j] - mu) * rs * g[c4 + j] + b[c4 + j];
            po[j] = 0.5f * xn * (1.f + erff(xn * 0.70710678118654752f));
        }
        wrow[i * 32 + lane] = o4;
    }
}

// ---------------------------- launch ------------------------------------
extern "C" void kernel_launch(void* const* d_in, const int* in_sizes, int n_in,
                              void* d_out, int out_size) {
    const float* x   = (const float*)d_in[0];
    const int*   q   = (const int*)d_in[1];
    const float* sc  = (const float*)d_in[2];
    const float* bia = (const float*)d_in[3];
    const float* la  = (const float*)d_in[4];
    const float* lbw = (const float*)d_in[5];
    const float* gam = (const float*)d_in[6];
    const float* bet = (const float*)d_in[7];
    float* out = (float*)d_out;

    float *W, *H, *Y, *U;
    cudaGetSymbolAddress((void**)&W, g_W);
    cudaGetSymbolAddress((void**)&H, g_H);
    cudaGetSymbolAddress((void**)&Y, g_Y);
    cudaGetSymbolAddress((void**)&U, g_U);

    k_dequant<<<6 * 1024 * 1024 / 256, 256>>>(q, sc);
    k_copy<<<32768, 256>>>((const float4*)x, (float4*)H, MTOT * DD / 4);

    for (int blk = 0; blk < 3; ++blk) {
        int l0 = 2 * blk, l1 = 2 * blk + 1;
        k_loraA<<<MTOT / 128, 128>>>(H, la + l0 * RR * DD, U);
        k_gemm<0><<<dim3(16, MTOT / 128), 256>>>(H, W + l0 * DD * DD, bia + l0 * DD,
                                                 lbw + l0 * DD * RR, U, nullptr, Y);
        k_lngelu<<<MTOT / 8, 256>>>(Y, gam + blk * DD, bet + blk * DD);
        k_loraA<<<MTOT / 128, 128>>>(Y, la + l1 * RR * DD, U);
        float* dst = (blk == 2) ? out : H;
        k_gemm<1><<<dim3(16, MTOT / 128), 256>>>(Y, W + l1 * DD * DD, bia + l1 * DD,
                                                 lbw + l1 * DD * RR, U, H, dst);
    }
}

// round 3
// speedup vs baseline: 1.0008x; 1.0008x over previous
#include <cuda_runtime.h>
#include <math.h>

#define MTOT 32768
#define DD   1024
#define RR   32

// ---------------- device scratch (no allocations allowed) ----------------
__device__ float g_W[6 * 1024 * 1024];   // dequantized weights [layer][out][in]
__device__ float g_H[MTOT * DD];         // hidden state h
__device__ float g_Y[MTOT * DD];         // intermediate y
__device__ float g_U[MTOT * RR];         // LoRA intermediate u = x @ la^T

// ---------------- dequant: w = (q/7.5 - 1) * scale[group] ----------------
__global__ void k_dequant(const int* __restrict__ q, const float* __restrict__ s) {
    int idx = blockIdx.x * 256 + threadIdx.x;      // over 6*1024*1024
    int in  = idx & 1023;
    int row = idx >> 10;                           // l*1024 + o
    float w = (float)q[idx] * (1.0f / 7.5f) - 1.0f;
    g_W[idx] = w * s[row * 64 + (in >> 4)];
}

__global__ void k_copy(const float4* __restrict__ src, float4* __restrict__ dst, int n4) {
    int i = blockIdx.x * 256 + threadIdx.x;
    if (i < n4) dst[i] = src[i];
}

// ---------------- LoRA-A: U[t,r] = sum_k A[t,k] * la[r,k] ----------------
// BM=128 tokens, N=32 (full), BK=32, 128 threads, thread tile 8x4
__global__ void __launch_bounds__(128) k_loraA(const float* __restrict__ A,
                                               const float* __restrict__ la,
                                               float* __restrict__ U) {
    __shared__ __align__(16) float As[32][132];
    __shared__ __align__(16) float Ls[32][36];
    int tid = threadIdx.x;
    int m0  = blockIdx.x * 128;
    int ty  = tid >> 3;   // 0..15 (m groups of 8)
    int tx  = tid & 7;    // 0..7  (r groups of 4)

    float acc[8][4] = {};
    float4 pa[8], pl[2];

    auto ldg = [&](int kt) {
        int k0 = kt * 32;
#pragma unroll
        for (int j = 0; j < 8; j++) {
            int idx = j * 128 + tid;              // 1024 float4s
            int row = idx >> 3, c = idx & 7;
            pa[j] = *(const float4*)(A + (m0 + row) * DD + k0 + c * 4);
        }
#pragma unroll
        for (int j = 0; j < 2; j++) {
            int idx = j * 128 + tid;              // 256 float4s
            int r = idx >> 3, kc = idx & 7;
            pl[j] = *(const float4*)(la + r * DD + k0 + kc * 4);
        }
    };
    auto sts = [&]() {
#pragma unroll
        for (int j = 0; j < 8; j++) {
            int idx = j * 128 + tid;
            int row = idx >> 3, c = idx & 7;
            As[c * 4 + 0][row] = pa[j].x; As[c * 4 + 1][row] = pa[j].y;
            As[c * 4 + 2][row] = pa[j].z; As[c * 4 + 3][row] = pa[j].w;
        }
#pragma unroll
        for (int j = 0; j < 2; j++) {
            int idx = j * 128 + tid;
            int r = idx >> 3, kc = idx & 7;
            Ls[kc * 4 + 0][r] = pl[j].x; Ls[kc * 4 + 1][r] = pl[j].y;
            Ls[kc * 4 + 2][r] = pl[j].z; Ls[kc * 4 + 3][r] = pl[j].w;
        }
    };

    ldg(0); sts(); __syncthreads();
    for (int kt = 0; kt < 32; ++kt) {
        if (kt + 1 < 32) ldg(kt + 1);
#pragma unroll
        for (int kk = 0; kk < 32; ++kk) {
            float a[8], b[4];
#pragma unroll
            for (int i = 0; i < 8; i++) a[i] = As[kk][ty * 8 + i];
#pragma unroll
            for (int j = 0; j < 4; j++) b[j] = Ls[kk][tx * 4 + j];
#pragma unroll
            for (int i = 0; i < 8; i++)
#pragma unroll
                for (int j = 0; j < 4; j++) acc[i][j] += a[i] * b[j];
        }
        __syncthreads();
        if (kt + 1 < 32) { sts(); __syncthreads(); }
    }
#pragma unroll
    for (int i = 0; i < 8; i++)
#pragma unroll
        for (int j = 0; j < 4; j++)
            U[(m0 + ty * 8 + i) * RR + tx * 4 + j] = acc[i][j];
}

// ---------------- main GEMM: C = A @ W^T + bias + U @ lb^T (+res) --------
// BM=128, BN=64, BK=16, 256 threads, thread tile 8x4, double-buffered smem
template <int MODE>  // 0: plain store, 1: add residual
__global__ void __launch_bounds__(256) k_gemm(const float* __restrict__ A,
                                              const float* __restrict__ W,
                                              const float* __restrict__ bias,
                                              const float* __restrict__ lb,
                                              const float* __restrict__ U,
                                              const float* res, float* C) {
    __shared__ __align__(16) float As[2][16][132];
    __shared__ __align__(16) float Bs[2][16][68];
    __shared__ __align__(16) float lbs[64][32];
    int tid = threadIdx.x;
    int n0  = blockIdx.x * 64;
    int m0  = blockIdx.y * 128;
    int ty  = tid >> 4;   // 0..15 (m)
    int tx  = tid & 15;   // 0..15 (n)

    // preload lb tile [64 outs][32 r]
#pragma unroll
    for (int j = 0; j < 2; j++) {
        int idx = j * 256 + tid;                  // 512 float4s
        int o = idx >> 3, rc = idx & 7;
        *(float4*)&lbs[o][rc * 4] = *(const float4*)(lb + (n0 + o) * RR + rc * 4);
    }

    float acc[8][4] = {};
    float4 pa[2], pb;

    auto ldg = [&](int kt) {
        int k0 = kt * 16;
#pragma unroll
        for (int j = 0; j < 2; j++) {
            int idx = j * 256 + tid;              // 512 float4s
            int row = idx >> 2, c = idx & 3;
            pa[j] = *(const float4*)(A + (m0 + row) * DD + k0 + c * 4);
        }
        {
            int row = tid >> 2, c = tid & 3;      // 256 float4s
            pb = *(const float4*)(W + (n0 + row) * DD + k0 + c * 4);
        }
    };
    auto sts = [&](int buf) {
#pragma unroll
        for (int j = 0; j < 2; j++) {
            int idx = j * 256 + tid;
            int row = idx >> 2, c = idx & 3;
            As[buf][c * 4 + 0][row] = pa[j].x; As[buf][c * 4 + 1][row] = pa[j].y;
            As[buf][c * 4 + 2][row] = pa[j].z; As[buf][c * 4 + 3][row] = pa[j].w;
        }
        {
            int row = tid >> 2, c = tid & 3;
            Bs[buf][c * 4 + 0][row] = pb.x; Bs[buf][c * 4 + 1][row] = pb.y;
            Bs[buf][c * 4 + 2][row] = pb.z; Bs[buf][c * 4 + 3][row] = pb.w;
        }
    };

    ldg(0); sts(0); __syncthreads();
    const int NKT = DD / 16;  // 64
    for (int kt = 0; kt < NKT; ++kt) {
        int cur = kt & 1;
        if (kt + 1 < NKT) ldg(kt + 1);
#pragma unroll
        for (int kk = 0; kk < 16; ++kk) {
            float4 a0 = *(const float4*)&As[cur][kk][ty * 8];
            float4 a1 = *(const float4*)&As[cur][kk][ty * 8 + 4];
            float4 b0 = *(const float4*)&Bs[cur][kk][tx * 4];
            float a[8] = {a0.x, a0.y, a0.z, a0.w, a1.x, a1.y, a1.z, a1.w};
            float b[4] = {b0.x, b0.y, b0.z, b0.w};
#pragma unroll
            for (int i = 0; i < 8; i++)
#pragma unroll
                for (int j = 0; j < 4; j++) acc[i][j] += a[i] * b[j];
        }
        if (kt + 1 < NKT) sts(cur ^ 1);
        __syncthreads();
    }

    // LoRA epilogue: stage U[128][32] into the (now free) As region
    float* Us = &As[0][0][0];                     // 4096 floats fit in 2*16*132
#pragma unroll
    for (int j = 0; j < 4; j++) {
        int idx = j * 256 + tid;                  // 1024 float4s
        int m = idx >> 3, rc = idx & 7;
        *(float4*)&Us[m * 32 + rc * 4] = *(const float4*)(U + (m0 + m) * RR + rc * 4);
    }
    __syncthreads();
#pragma unroll
    for (int r = 0; r < RR; ++r) {
        float bv[4];
#pragma unroll
        for (int j = 0; j < 4; j++) bv[j] = lbs[tx * 4 + j][r];
#pragma unroll
        for (int i = 0; i < 8; i++) {
            float uv = Us[(ty * 8 + i) * 32 + r];
#pragma unroll
            for (int j = 0; j < 4; j++) acc[i][j] += uv * bv[j];
        }
    }

    float bcol[4];
#pragma unroll
    for (int j = 0; j < 4; j++) bcol[j] = bias[n0 + tx * 4 + j];
#pragma unroll
    for (int i = 0; i < 8; i++) {
        int row = m0 + ty * 8 + i;
#pragma unroll
        for (int j = 0; j < 4; j++) {
            int col = n0 + tx * 4 + j;
            float v = acc[i][j] + bcol[j];
            if (MODE == 1) v += res[row * DD + col];
            C[row * DD + col] = v;
        }
    }
}

// ---------------- LayerNorm + exact GELU, warp per token -----------------
__global__ void __launch_bounds__(256) k_lngelu(float* Y, const float* __restrict__ g,
                                                const float* __restrict__ b) {
    int warp = threadIdx.x >> 5, lane = threadIdx.x & 31;
    int t = blockIdx.x * 8 + warp;
    const float4* row = (const float4*)(Y + t * DD);
    float4 v[8];
    float s = 0.f, sq = 0.f;
#pragma unroll
    for (int i = 0; i < 8; i++) {
        v[i] = row[i * 32 + lane];
        s  += v[i].x + v[i].y + v[i].z + v[i].w;
        sq += v[i].x * v[i].x + v[i].y * v[i].y + v[i].z * v[i].z + v[i].w * v[i].w;
    }
#pragma unroll
    for (int o = 16; o > 0; o >>= 1) {
        s  += __shfl_xor_sync(0xffffffffu, s, o);
        sq += __shfl_xor_sync(0xffffffffu, sq, o);
    }
    float mu  = s * (1.f / 1024.f);
    float var = sq * (1.f / 1024.f) - mu * mu;
    float rs  = rsqrtf(var + 1e-5f);
    float4* wrow = (float4*)(Y + t * DD);
#pragma unroll
    for (int i = 0; i < 8; i++) {
        int c4 = (i * 32 + lane) * 4;
        float x[4] = {v[i].x, v[i].y, v[i].z, v[i].w};
        float4 o4;
        float* po = &o4.x;
#pragma unroll
        for (int j = 0; j < 4; j++) {
            float xn = (x[j] - mu) * rs * g[c4 + j] + b[c4 + j];
            po[j] = 0.5f * xn * (1.f + erff(xn * 0.70710678118654752f));
        }
        wrow[i * 32 + lane] = o4;
    }
}

// ---------------------------- launch ------------------------------------
extern "C" void kernel_launch(void* const* d_in, const int* in_sizes, int n_in,
                              void* d_out, int out_size) {
    const float* x   = (const float*)d_in[0];
    const int*   q   = (const int*)d_in[1];
    const float* sc  = (const float*)d_in[2];
    const float* bia = (const float*)d_in[3];
    const float* la  = (const float*)d_in[4];
    const float* lbw = (const float*)d_in[5];
    const float* gam = (const float*)d_in[6];
    const float* bet = (const float*)d_in[7];
    float* out = (float*)d_out;

    float *W, *H, *Y, *U;
    cudaGetSymbolAddress((void**)&W, g_W);
    cudaGetSymbolAddress((void**)&H, g_H);
    cudaGetSymbolAddress((void**)&Y, g_Y);
    cudaGetSymbolAddress((void**)&U, g_U);

    k_dequant<<<6 * 1024 * 1024 / 256, 256>>>(q, sc);
    k_copy<<<32768, 256>>>((const float4*)x, (float4*)H, MTOT * DD / 4);

    for (int blk = 0; blk < 3; ++blk) {
        int l0 = 2 * blk, l1 = 2 * blk + 1;
        k_loraA<<<MTOT / 128, 128>>>(H, la + l0 * RR * DD, U);
        k_gemm<0><<<dim3(16, MTOT / 128), 256>>>(H, W + l0 * DD * DD, bia + l0 * DD,
                                                 lbw + l0 * DD * RR, U, nullptr, Y);
        k_lngelu<<<MTOT / 8, 256>>>(Y, gam + blk * DD, bet + blk * DD);
        k_loraA<<<MTOT / 128, 128>>>(Y, la + l1 * RR * DD, U);
        float* dst = (blk == 2) ? out : H;
        k_gemm<1><<<dim3(16, MTOT / 128), 256>>>(Y, W + l1 * DD * DD, bia + l1 * DD,
                                                 lbw + l1 * DD * RR, U, H, dst);
    }
}

// round 5
// speedup vs baseline: 1.8735x; 1.8719x over previous
#include <cuda_runtime.h>
#include <cuda_bf16.h>
#include <math.h>
#include <stdint.h>

#define MTOT 32768
#define DD   1024
#define KP   1088
#define RR   32

// ---------------- device scratch (no allocations allowed) ----------------
__device__ __align__(1024) __nv_bfloat16 g_Sh0[MTOT * KP];
__device__ __align__(1024) __nv_bfloat16 g_Sl0[MTOT * KP];
__device__ __align__(1024) __nv_bfloat16 g_Sh1[MTOT * KP];
__device__ __align__(1024) __nv_bfloat16 g_Sl1[MTOT * KP];
__device__ __align__(1024) __nv_bfloat16 g_Wh[6 * DD * KP];
__device__ __align__(1024) __nv_bfloat16 g_Wl[6 * DD * KP];
__device__ __align__(1024) __nv_bfloat16 g_La[6 * 64 * KP];
__device__ float g_H[MTOT * DD];
__device__ float g_Y[MTOT * DD];

// ------------------------------ helpers ----------------------------------
__device__ __forceinline__ uint32_t s2u(const void* p) {
    uint32_t a;
    asm("{ .reg .u64 t; cvta.to.shared.u64 t, %1; cvt.u32.u64 %0, t; }" : "=r"(a) : "l"(p));
    return a;
}
__device__ __forceinline__ void cpa(uint32_t s, const void* g) {
    asm volatile("cp.async.cg.shared.global [%0], [%1], 16;" :: "r"(s), "l"(g) : "memory");
}
__device__ __forceinline__ void ldsm4(uint32_t* r, uint32_t a) {
    asm volatile("ldmatrix.sync.aligned.m8n8.x4.shared.b16 {%0,%1,%2,%3}, [%4];"
                 : "=r"(r[0]), "=r"(r[1]), "=r"(r[2]), "=r"(r[3]) : "r"(a));
}
__device__ __forceinline__ void mma16816(float* c, const uint32_t* a, const uint32_t* b) {
    asm volatile(
        "mma.sync.aligned.m16n8k16.row.col.f32.bf16.bf16.f32 "
        "{%0,%1,%2,%3}, {%4,%5,%6,%7}, {%8,%9}, {%0,%1,%2,%3};"
        : "+f"(c[0]), "+f"(c[1]), "+f"(c[2]), "+f"(c[3])
        : "r"(a[0]), "r"(a[1]), "r"(a[2]), "r"(a[3]), "r"(b[0]), "r"(b[1]));
}
__device__ __forceinline__ uint32_t pack2(float a, float b) {
    __nv_bfloat16 x = __float2bfloat16(a), y = __float2bfloat16(b);
    return (uint32_t)__bfloat16_as_ushort(x) | ((uint32_t)__bfloat16_as_ushort(y) << 16);
}
__device__ __forceinline__ uint32_t swz(uint32_t o) { return o ^ ((o >> 3) & 0x70); }

// ------------------- prep: dequant + split weights (+lb concat) ----------
__global__ void k_prepw(const int* __restrict__ q, const float* __restrict__ s,
                        const float* __restrict__ lb) {
    int idx = blockIdx.x * 256 + threadIdx.x;
    int i = idx % KP, row = idx / KP;   // row = l*DD + o
    float w;
    if (i < 1024)      w = ((float)q[row * DD + i] * (1.0f / 7.5f) - 1.0f) * s[row * 64 + (i >> 4)];
    else if (i < 1056) w = lb[row * RR + (i - 1024)];
    else               w = 0.0f;
    __nv_bfloat16 hi = __float2bfloat16(w);
    g_Wh[idx] = hi;
    g_Wl[idx] = __float2bfloat16(w - __bfloat162float(hi));
}
__global__ void k_prepla(const float* __restrict__ la) {
    int idx = blockIdx.x * 256 + threadIdx.x;
    int i = idx % KP, rem = idx / KP;
    int r = rem % 64, l = rem / 64;
    float v = (r < RR && i < 1024) ? la[(l * RR + r) * DD + i] : 0.0f;
    g_La[idx] = __float2bfloat16(v);
}
// x -> g_H (fp32) + splits into buffer 0
__global__ void k_convert(const float* __restrict__ X) {
    int t = blockIdx.x * 256 + threadIdx.x;
    int m = t >> 8, c4 = (t & 255) * 4;
    float4 v = ((const float4*)X)[t];
    ((float4*)g_H)[t] = v;
    float h0 = __bfloat162float(__float2bfloat16(v.x));
    float h1 = __bfloat162float(__float2bfloat16(v.y));
    float h2 = __bfloat162float(__float2bfloat16(v.z));
    float h3 = __bfloat162float(__float2bfloat16(v.w));
    uint2 uh = {pack2(v.x, v.y), pack2(v.z, v.w)};
    uint2 ul = {pack2(v.x - h0, v.y - h1), pack2(v.z - h2, v.w - h3)};
    *(uint2*)&g_Sh0[(size_t)m * KP + c4] = uh;
    *(uint2*)&g_Sl0[(size_t)m * KP + c4] = ul;
}

// ---------------- LayerNorm + exact GELU -> splits -----------------------
__global__ void __launch_bounds__(256) k_lngelu(const float* __restrict__ Y,
                                                const float* __restrict__ g,
                                                const float* __restrict__ b,
                                                __nv_bfloat16* __restrict__ oh,
                                                __nv_bfloat16* __restrict__ ol) {
    int warp = threadIdx.x >> 5, lane = threadIdx.x & 31;
    int t = blockIdx.x * 8 + warp;
    const float4* row = (const float4*)(Y + (size_t)t * DD);
    float4 v[8];
    float s = 0.f, sq = 0.f;
#pragma unroll
    for (int i = 0; i < 8; i++) {
        v[i] = row[i * 32 + lane];
        s  += v[i].x + v[i].y + v[i].z + v[i].w;
        sq += v[i].x * v[i].x + v[i].y * v[i].y + v[i].z * v[i].z + v[i].w * v[i].w;
    }
#pragma unroll
    for (int o = 16; o > 0; o >>= 1) {
        s  += __shfl_xor_sync(0xffffffffu, s, o);
        sq += __shfl_xor_sync(0xffffffffu, sq, o);
    }
    float mu  = s * (1.f / 1024.f);
    float var = sq * (1.f / 1024.f) - mu * mu;
    float rs  = rsqrtf(var + 1e-5f);
#pragma unroll
    for (int i = 0; i < 8; i++) {
        int c4 = (i * 32 + lane) * 4;
        float xv[4] = {v[i].x, v[i].y, v[i].z, v[i].w};
        float yv[4];
#pragma unroll
        for (int j = 0; j < 4; j++) {
            float xn = (xv[j] - mu) * rs * g[c4 + j] + b[c4 + j];
            yv[j] = 0.5f * xn * (1.f + erff(xn * 0.70710678118654752f));
        }
        float h0 = __bfloat162float(__float2bfloat16(yv[0]));
        float h1 = __bfloat162float(__float2bfloat16(yv[1]));
        float h2 = __bfloat162float(__float2bfloat16(yv[2]));
        float h3 = __bfloat162float(__float2bfloat16(yv[3]));
        uint2 uh = {pack2(yv[0], yv[1]), pack2(yv[2], yv[3])};
        uint2 ul = {pack2(yv[0] - h0, yv[1] - h1), pack2(yv[2] - h2, yv[3] - h3)};
        *(uint2*)&oh[(size_t)t * KP + c4] = uh;
        *(uint2*)&ol[(size_t)t * KP + c4] = ul;
    }
}

// -------------------- mma.sync bf16 GEMM, cp.async ring ------------------
// D[128, NT] = A[128, K] @ B[NT, K]^T  with 3-term bf16 split (if S3).
// MODE 0: dst = D + bias (fp32)
// MODE 1: dst = D + bias + res (fp32), also write splits of dst to ShO/SlO cols [n0..)
// MODE 2: write D as bf16 hi/lo into ShO/SlO cols [1024 + n0 ..)
template <int NT, int NKT, bool S3, int MODE>
__global__ void __launch_bounds__(256, 1) k_gemm(
    const __nv_bfloat16* __restrict__ Ah_g, const __nv_bfloat16* __restrict__ Al_g,
    const __nv_bfloat16* __restrict__ Bh_g, const __nv_bfloat16* __restrict__ Bl_g,
    const float* __restrict__ bias, const float* __restrict__ res,
    float* __restrict__ dst,
    __nv_bfloat16* __restrict__ ShO, __nv_bfloat16* __restrict__ SlO)
{
    constexpr int NG   = NT / 32;                       // n-groups per warp
    constexpr int OF_AL = 16384;
    constexpr int OF_BH = S3 ? 32768 : 16384;
    constexpr int OF_BL = OF_BH + NT * 128;
    constexpr int STG   = OF_BH + NT * 128 * (S3 ? 2 : 1);

    extern __shared__ char smem[];
    uint32_t ab = (s2u(smem) + 1023u) & ~1023u;

    int tid = threadIdx.x, wid = tid >> 5, lane = tid & 31;
    int n0 = blockIdx.x * NT;
    int m0 = blockIdx.y * 128;
    int wm = wid & 1, wn = wid >> 1;                    // 2 x 4 warp grid

    auto ldst = [&](int kt, int s) {
        uint32_t base = ab + s * STG;
        size_t kb = (size_t)kt * 128;
        const char* pAh = (const char*)Ah_g + (size_t)m0 * (KP * 2) + kb;
        const char* pAl = (const char*)Al_g + (size_t)m0 * (KP * 2) + kb;
        const char* pBh = (const char*)Bh_g + (size_t)n0 * (KP * 2) + kb;
        const char* pBl = (const char*)Bl_g + (size_t)n0 * (KP * 2) + kb;
#pragma unroll
        for (int j = 0; j < 4; j++) {                   // A: 128 rows x 8 chunks
            int c = j * 256 + tid, row = c >> 3, qq = c & 7;
            uint32_t off = swz((uint32_t)(row * 128 + qq * 16));
            cpa(base + off, pAh + (size_t)row * (KP * 2) + qq * 16);
            if (S3) cpa(base + OF_AL + off, pAl + (size_t)row * (KP * 2) + qq * 16);
        }
#pragma unroll
        for (int j = 0; j < NT / 32; j++) {             // B: NT rows x 8 chunks
            int c = j * 256 + tid, row = c >> 3, qq = c & 7;
            uint32_t off = swz((uint32_t)(row * 128 + qq * 16));
            cpa(base + OF_BH + off, pBh + (size_t)row * (KP * 2) + qq * 16);
            if (S3) cpa(base + OF_BL + off, pBl + (size_t)row * (KP * 2) + qq * 16);
        }
        asm volatile("cp.async.commit_group;" ::: "memory");
    };

    float acc[4][NG][4];
#pragma unroll
    for (int i = 0; i < 4; i++)
#pragma unroll
        for (int j = 0; j < NG; j++)
#pragma unroll
            for (int q = 0; q < 4; q++) acc[i][j][q] = 0.f;

    ldst(0, 0); ldst(1, 1); ldst(2, 2);

    for (int k = 0; k < NKT; k++) {
        const int s = k % 3;
        asm volatile("cp.async.wait_group 2;" ::: "memory");
        __syncthreads();
        uint32_t aB = ab + s * STG;
        uint32_t bB = aB + OF_BH;
#pragma unroll
        for (int kc = 0; kc < 4; kc++) {
            uint32_t ah[4][4], al[4][4], bh[NG][2], bl[NG][2];
            uint32_t arow = (uint32_t)(wm * 64 + (lane & 15));
            uint32_t abyte = (uint32_t)(kc * 32 + ((lane >> 4) << 4));
#pragma unroll
            for (int mg = 0; mg < 4; mg++) {
                uint32_t off = swz((arow + mg * 16) * 128 + abyte);
                ldsm4(ah[mg], aB + off);
                if (S3) ldsm4(al[mg], aB + OF_AL - OF_BH + bB - aB + off);  // aB+OF_AL+off
            }
            if (S3) {
                // recompute cleanly (the line above simplifies to aB+OF_AL+off)
            }
            uint32_t nbyte = (uint32_t)(kc * 32 + (((lane >> 3) & 1) << 4));
#pragma unroll
            for (int nh = 0; nh < NG / 2; nh++) {
                uint32_t nrow = (uint32_t)(wn * (NT / 4) + nh * 16 + ((lane >> 4) << 3) + (lane & 7));
                uint32_t off = swz(nrow * 128 + nbyte);
                uint32_t r[4];
                ldsm4(r, bB + off);
                bh[nh * 2][0] = r[0]; bh[nh * 2][1] = r[1];
                bh[nh * 2 + 1][0] = r[2]; bh[nh * 2 + 1][1] = r[3];
                if (S3) {
                    ldsm4(r, aB + OF_BL + off);
                    bl[nh * 2][0] = r[0]; bl[nh * 2][1] = r[1];
                    bl[nh * 2 + 1][0] = r[2]; bl[nh * 2 + 1][1] = r[3];
                }
            }
#pragma unroll
            for (int mg = 0; mg < 4; mg++)
#pragma unroll
                for (int ng = 0; ng < NG; ng++) {
                    mma16816(acc[mg][ng], ah[mg], bh[ng]);
                    if (S3) {
                        mma16816(acc[mg][ng], ah[mg], bl[ng]);
                        mma16816(acc[mg][ng], al[mg], bh[ng]);
                    }
                }
        }
        __syncthreads();
        if (k + 3 < NKT) ldst(k + 3, s);
    }

    // ------------------------------- epilogue ----------------------------
    int t4 = lane >> 2, t2 = (lane & 3) * 2;
#pragma unroll
    for (int mg = 0; mg < 4; mg++)
#pragma unroll
        for (int ng = 0; ng < NG; ng++) {
            float* c = acc[mg][ng];
            int col = n0 + wn * (NT / 4) + ng * 8 + t2;
#pragma unroll
            for (int hh = 0; hh < 2; hh++) {
                int row = m0 + wm * 64 + mg * 16 + t4 + hh * 8;
                float f0 = c[hh * 2], f1 = c[hh * 2 + 1];
                if (MODE == 2) {
                    __nv_bfloat16 h0 = __float2bfloat16(f0), h1 = __float2bfloat16(f1);
                    uint32_t hp = (uint32_t)__bfloat16_as_ushort(h0) |
                                  ((uint32_t)__bfloat16_as_ushort(h1) << 16);
                    uint32_t lp = pack2(f0 - __bfloat162float(h0), f1 - __bfloat162float(h1));
                    *(uint32_t*)&ShO[(size_t)row * KP + 1024 + col] = hp;
                    *(uint32_t*)&SlO[(size_t)row * KP + 1024 + col] = lp;
                } else {
                    float2 b2 = *(const float2*)&bias[col];
                    float v0 = f0 + b2.x, v1 = f1 + b2.y;
                    if (MODE == 1) {
                        float2 r2 = *(const float2*)&res[(size_t)row * DD + col];
                        v0 += r2.x; v1 += r2.y;
                    }
                    float2 o2 = {v0, v1};
                    *(float2*)&dst[(size_t)row * DD + col] = o2;
                    if (MODE == 1) {
                        __nv_bfloat16 h0 = __float2bfloat16(v0), h1 = __float2bfloat16(v1);
                        uint32_t hp = (uint32_t)__bfloat16_as_ushort(h0) |
                                      ((uint32_t)__bfloat16_as_ushort(h1) << 16);
                        uint32_t lp = pack2(v0 - __bfloat162float(h0), v1 - __bfloat162float(h1));
                        *(uint32_t*)&ShO[(size_t)row * KP + col] = hp;
                        *(uint32_t*)&SlO[(size_t)row * KP + col] = lp;
                    }
                }
            }
        }
}

// ------------------------------- launch ----------------------------------
extern "C" void kernel_launch(void* const* d_in, const int* in_sizes, int n_in,
                              void* d_out, int out_size) {
    const float* x   = (const float*)d_in[0];
    const int*   q   = (const int*)d_in[1];
    const float* sc  = (const float*)d_in[2];
    const float* bia = (const float*)d_in[3];
    const float* la  = (const float*)d_in[4];
    const float* lbw = (const float*)d_in[5];
    const float* gam = (const float*)d_in[6];
    const float* bet = (const float*)d_in[7];
    float* out = (float*)d_out;

    __nv_bfloat16 *Wh, *Wl, *La, *Sh[2], *Sl[2];
    float *H, *Y;
    cudaGetSymbolAddress((void**)&Wh, g_Wh);
    cudaGetSymbolAddress((void**)&Wl, g_Wl);
    cudaGetSymbolAddress((void**)&La, g_La);
    cudaGetSymbolAddress((void**)&Sh[0], g_Sh0);
    cudaGetSymbolAddress((void**)&Sl[0], g_Sl0);
    cudaGetSymbolAddress((void**)&Sh[1], g_Sh1);
    cudaGetSymbolAddress((void**)&Sl[1], g_Sl1);
    cudaGetSymbolAddress((void**)&H,  g_H);
    cudaGetSymbolAddress((void**)&Y,  g_Y);

    const int SM_MAIN = 1024 + 3 * 65536;   // 197632
    const int SM_LORA = 1024 + 3 * 24576;   // 74752
    cudaFuncSetAttribute(k_gemm<128, 17, true, 0>, cudaFuncAttributeMaxDynamicSharedMemorySize, SM_MAIN);
    cudaFuncSetAttribute(k_gemm<128, 17, true, 1>, cudaFuncAttributeMaxDynamicSharedMemorySize, SM_MAIN);
    cudaFuncSetAttribute(k_gemm<64, 16, false, 2>, cudaFuncAttributeMaxDynamicSharedMemorySize, SM_LORA);

    k_prepw<<<6 * DD * KP / 256, 256>>>(q, sc, lbw);
    k_prepla<<<6 * 64 * KP / 256, 256>>>(la);
    k_convert<<<MTOT * DD / 4 / 256, 256>>>(x);

    int p = 0;
    for (int blk = 0; blk < 3; ++blk) {
        int l0 = 2 * blk, l1 = 2 * blk + 1;
        // LoRA-A #1: U -> cols 1024.. of buffer p (reads only cols 0..1023)
        k_gemm<64, 16, false, 2><<<dim3(1, MTOT / 128), 256, SM_LORA>>>(
            Sh[p], nullptr, La + (size_t)l0 * 64 * KP, nullptr,
            nullptr, nullptr, nullptr, Sh[p], Sl[p]);
        // main GEMM #1 -> Y (fp32)
        k_gemm<128, 17, true, 0><<<dim3(8, MTOT / 128), 256, SM_MAIN>>>(
            Sh[p], Sl[p], Wh + (size_t)l0 * DD * KP, Wl + (size_t)l0 * DD * KP,
            bia + l0 * DD, nullptr, Y, nullptr, nullptr);
        // LN + GELU -> splits into buffer p (cols 0..1023)
        k_lngelu<<<MTOT / 8, 256>>>(Y, gam + blk * DD, bet + blk * DD, Sh[p], Sl[p]);
        // LoRA-A #2
        k_gemm<64, 16, false, 2><<<dim3(1, MTOT / 128), 256, SM_LORA>>>(
            Sh[p], nullptr, La + (size_t)l1 * 64 * KP, nullptr,
            nullptr, nullptr, nullptr, Sh[p], Sl[p]);
        // main GEMM #2 + residual -> dst fp32, splits -> buffer p^1
        float* dst = (blk == 2) ? out : H;
        k_gemm<128, 17, true, 1><<<dim3(8, MTOT / 128), 256, SM_MAIN>>>(
            Sh[p], Sl[p], Wh + (size_t)l1 * DD * KP, Wl + (size_t)l1 * DD * KP,
            bia + l1 * DD, H, dst, Sh[p ^ 1], Sl[p ^ 1]);
        p ^= 1;
    }
}

// round 7
// speedup vs baseline: 2.7534x; 1.4697x over previous
#include <cuda_runtime.h>
#include <cuda_bf16.h>
#include <math.h>
#include <stdint.h>

#define MTOT 32768
#define DD   1024
#define KP   1088
#define RR   32

// ---------------- device scratch (no allocations allowed) ----------------
__device__ __align__(1024) __nv_bfloat16 g_Sh0[MTOT * KP];
__device__ __align__(1024) __nv_bfloat16 g_Sl0[MTOT * KP];
__device__ __align__(1024) __nv_bfloat16 g_Sh1[MTOT * KP];
__device__ __align__(1024) __nv_bfloat16 g_Sl1[MTOT * KP];
__device__ __align__(1024) __nv_bfloat16 g_Wh[6 * DD * KP];
__device__ __align__(1024) __nv_bfloat16 g_Wl[6 * DD * KP];
__device__ __align__(1024) __nv_bfloat16 g_La[6 * 64 * KP];
__device__ float g_H[MTOT * DD];
__device__ float g_Y[MTOT * DD];

// ------------------------------ helpers ----------------------------------
__device__ __forceinline__ uint32_t s2u(const void* p) {
    uint32_t a;
    asm("{ .reg .u64 t; cvta.to.shared.u64 t, %1; cvt.u32.u64 %0, t; }" : "=r"(a) : "l"(p));
    return a;
}
__device__ __forceinline__ void cpa(uint32_t s, const void* g) {
    asm volatile("cp.async.cg.shared.global [%0], [%1], 16;" :: "r"(s), "l"(g) : "memory");
}
__device__ __forceinline__ void ldsm4(uint32_t* r, uint32_t a) {
    asm volatile("ldmatrix.sync.aligned.m8n8.x4.shared.b16 {%0,%1,%2,%3}, [%4];"
                 : "=r"(r[0]), "=r"(r[1]), "=r"(r[2]), "=r"(r[3]) : "r"(a));
}
__device__ __forceinline__ void mma16816(float* c, const uint32_t* a, const uint32_t* b) {
    asm volatile(
        "mma.sync.aligned.m16n8k16.row.col.f32.bf16.bf16.f32 "
        "{%0,%1,%2,%3}, {%4,%5,%6,%7}, {%8,%9}, {%0,%1,%2,%3};"
        : "+f"(c[0]), "+f"(c[1]), "+f"(c[2]), "+f"(c[3])
        : "r"(a[0]), "r"(a[1]), "r"(a[2]), "r"(a[3]), "r"(b[0]), "r"(b[1]));
}
__device__ __forceinline__ uint32_t pack2(float a, float b) {
    __nv_bfloat16 x = __float2bfloat16(a), y = __float2bfloat16(b);
    return (uint32_t)__bfloat16_as_ushort(x) | ((uint32_t)__bfloat16_as_ushort(y) << 16);
}
__device__ __forceinline__ uint32_t swz(uint32_t o) { return o ^ ((o >> 3) & 0x70); }

// ------------------- prep: dequant + split weights (+lb concat) ----------
__global__ void k_prepw(const int* __restrict__ q, const float* __restrict__ s,
                        const float* __restrict__ lb) {
    int idx = blockIdx.x * 256 + threadIdx.x;
    int i = idx % KP, row = idx / KP;   // row = l*DD + o
    float w;
    if (i < 1024)      w = ((float)q[row * DD + i] * (1.0f / 7.5f) - 1.0f) * s[row * 64 + (i >> 4)];
    else if (i < 1056) w = lb[row * RR + (i - 1024)];
    else               w = 0.0f;
    __nv_bfloat16 hi = __float2bfloat16(w);
    g_Wh[idx] = hi;
    g_Wl[idx] = __float2bfloat16(w - __bfloat162float(hi));
}
__global__ void k_prepla(const float* __restrict__ la) {
    int idx = blockIdx.x * 256 + threadIdx.x;
    int i = idx % KP, rem = idx / KP;
    int r = rem % 64, l = rem / 64;
    float v = (r < RR && i < 1024) ? la[(l * RR + r) * DD + i] : 0.0f;
    g_La[idx] = __float2bfloat16(v);
}
// x -> g_H (fp32) + splits into buffer 0
__global__ void k_convert(const float* __restrict__ X) {
    int t = blockIdx.x * 256 + threadIdx.x;
    int m = t >> 8, c4 = (t & 255) * 4;
    float4 v = ((const float4*)X)[t];
    ((float4*)g_H)[t] = v;
    float h0 = __bfloat162float(__float2bfloat16(v.x));
    float h1 = __bfloat162float(__float2bfloat16(v.y));
    float h2 = __bfloat162float(__float2bfloat16(v.z));
    float h3 = __bfloat162float(__float2bfloat16(v.w));
    uint2 uh = {pack2(v.x, v.y), pack2(v.z, v.w)};
    uint2 ul = {pack2(v.x - h0, v.y - h1), pack2(v.z - h2, v.w - h3)};
    *(uint2*)&g_Sh0[(size_t)m * KP + c4] = uh;
    *(uint2*)&g_Sl0[(size_t)m * KP + c4] = ul;
}

// ---------------- LayerNorm + exact GELU -> splits -----------------------
__global__ void __launch_bounds__(256) k_lngelu(const float* __restrict__ Y,
                                                const float* __restrict__ g,
                                                const float* __restrict__ b,
                                                __nv_bfloat16* __restrict__ oh,
                                                __nv_bfloat16* __restrict__ ol) {
    int warp = threadIdx.x >> 5, lane = threadIdx.x & 31;
    int t = blockIdx.x * 8 + warp;
    const float4* row = (const float4*)(Y + (size_t)t * DD);
    float4 v[8];
    float s = 0.f, sq = 0.f;
#pragma unroll
    for (int i = 0; i < 8; i++) {
        v[i] = row[i * 32 + lane];
        s  += v[i].x + v[i].y + v[i].z + v[i].w;
        sq += v[i].x * v[i].x + v[i].y * v[i].y + v[i].z * v[i].z + v[i].w * v[i].w;
    }
#pragma unroll
    for (int o = 16; o > 0; o >>= 1) {
        s  += __shfl_xor_sync(0xffffffffu, s, o);
        sq += __shfl_xor_sync(0xffffffffu, sq, o);
    }
    float mu  = s * (1.f / 1024.f);
    float var = sq * (1.f / 1024.f) - mu * mu;
    float rs  = rsqrtf(var + 1e-5f);
#pragma unroll
    for (int i = 0; i < 8; i++) {
        int c4 = (i * 32 + lane) * 4;
        float xv[4] = {v[i].x, v[i].y, v[i].z, v[i].w};
        float yv[4];
#pragma unroll
        for (int j = 0; j < 4; j++) {
            float xn = (xv[j] - mu) * rs * g[c4 + j] + b[c4 + j];
            yv[j] = 0.5f * xn * (1.f + erff(xn * 0.70710678118654752f));
        }
        float h0 = __bfloat162float(__float2bfloat16(yv[0]));
        float h1 = __bfloat162float(__float2bfloat16(yv[1]));
        float h2 = __bfloat162float(__float2bfloat16(yv[2]));
        float h3 = __bfloat162float(__float2bfloat16(yv[3]));
        uint2 uh = {pack2(yv[0], yv[1]), pack2(yv[2], yv[3])};
        uint2 ul = {pack2(yv[0] - h0, yv[1] - h1), pack2(yv[2] - h2, yv[3] - h3)};
        *(uint2*)&oh[(size_t)t * KP + c4] = uh;
        *(uint2*)&ol[(size_t)t * KP + c4] = ul;
    }
}

// -------------------- mma.sync bf16 GEMM, cp.async ring ------------------
// 512 threads, 16 warps in 4x4 grid; warp tile 32 x (NT/4).
// MODE 0: dst = D + bias (fp32)
// MODE 1: dst = D + bias + res (fp32), also write splits of dst to ShO/SlO
// MODE 2: write D as bf16 hi/lo into ShO/SlO cols [1024 + n0 ..)
template <int NT, int NKT, bool S3, int MODE>
__global__ void __launch_bounds__(512, 1) k_gemm(
    const __nv_bfloat16* __restrict__ Ah_g, const __nv_bfloat16* __restrict__ Al_g,
    const __nv_bfloat16* __restrict__ Bh_g, const __nv_bfloat16* __restrict__ Bl_g,
    const float* __restrict__ bias, const float* __restrict__ res,
    float* __restrict__ dst,
    __nv_bfloat16* __restrict__ ShO, __nv_bfloat16* __restrict__ SlO)
{
    constexpr int NG    = NT / 32;                      // n 8-col groups per warp
    constexpr int OF_AL = 16384;
    constexpr int OF_BH = S3 ? 32768 : 16384;
    constexpr int OF_BL = OF_BH + NT * 128;
    constexpr int STG   = OF_BH + NT * 128 * (S3 ? 2 : 1);

    extern __shared__ char smem[];
    uint32_t ab = (s2u(smem) + 1023u) & ~1023u;

    int tid = threadIdx.x, wid = tid >> 5, lane = tid & 31;
    int n0 = blockIdx.x * NT;
    int m0 = blockIdx.y * 128;
    int wm = wid & 3, wn = wid >> 2;                    // 4 x 4 warp grid

    auto ldst = [&](int kt, int s) {
        uint32_t base = ab + s * STG;
        size_t kb = (size_t)kt * 128;
        const char* pAh = (const char*)Ah_g + (size_t)m0 * (KP * 2) + kb;
        const char* pAl = (const char*)Al_g + (size_t)m0 * (KP * 2) + kb;
        const char* pBh = (const char*)Bh_g + (size_t)n0 * (KP * 2) + kb;
        const char* pBl = (const char*)Bl_g + (size_t)n0 * (KP * 2) + kb;
#pragma unroll
        for (int j = 0; j < 2; j++) {                   // A: 128 rows x 8 chunks
            int c = j * 512 + tid, row = c >> 3, qq = c & 7;
            uint32_t off = swz((uint32_t)(row * 128 + qq * 16));
            cpa(base + off, pAh + (size_t)row * (KP * 2) + qq * 16);
            if (S3) cpa(base + OF_AL + off, pAl + (size_t)row * (KP * 2) + qq * 16);
        }
#pragma unroll
        for (int j = 0; j < NT / 64; j++) {             // B: NT rows x 8 chunks
            int c = j * 512 + tid, row = c >> 3, qq = c & 7;
            uint32_t off = swz((uint32_t)(row * 128 + qq * 16));
            cpa(base + OF_BH + off, pBh + (size_t)row * (KP * 2) + qq * 16);
            if (S3) cpa(base + OF_BL + off, pBl + (size_t)row * (KP * 2) + qq * 16);
        }
        asm volatile("cp.async.commit_group;" ::: "memory");
    };

    float acc[2][NG][4];
#pragma unroll
    for (int i = 0; i < 2; i++)
#pragma unroll
        for (int j = 0; j < NG; j++)
#pragma unroll
            for (int q = 0; q < 4; q++) acc[i][j][q] = 0.f;

    ldst(0, 0); ldst(1, 1);

    for (int k = 0; k < NKT; k++) {
        const int s = k % 3;
        asm volatile("cp.async.wait_group 1;" ::: "memory");
        __syncthreads();
        if (k + 2 < NKT) ldst(k + 2, (k + 2) % 3);      // slot consumed last iter
        uint32_t aB = ab + s * STG;
        uint32_t bB = aB + OF_BH;
#pragma unroll
        for (int kc = 0; kc < 4; kc++) {
            uint32_t ah[2][4], al[2][4], bh[NG][2], bl[NG][2];
            uint32_t arow = (uint32_t)(wm * 32 + (lane & 15));
            uint32_t abyte = (uint32_t)(kc * 32 + ((lane >> 4) << 4));
#pragma unroll
            for (int mg = 0; mg < 2; mg++) {
                uint32_t off = swz((arow + mg * 16) * 128 + abyte);
                ldsm4(ah[mg], aB + off);
                if (S3) ldsm4(al[mg], aB + OF_AL + off);
            }
            uint32_t nbyte = (uint32_t)(kc * 32 + (((lane >> 3) & 1) << 4));
#pragma unroll
            for (int nh = 0; nh < NG / 2; nh++) {
                uint32_t nrow = (uint32_t)(wn * (NT / 4) + nh * 16 + ((lane >> 4) << 3) + (lane & 7));
                uint32_t off = swz(nrow * 128 + nbyte);
                uint32_t r[4];
                ldsm4(r, bB + off);
                bh[nh * 2][0] = r[0]; bh[nh * 2][1] = r[1];
                bh[nh * 2 + 1][0] = r[2]; bh[nh * 2 + 1][1] = r[3];
                if (S3) {
                    ldsm4(r, aB + OF_BL + off);
                    bl[nh * 2][0] = r[0]; bl[nh * 2][1] = r[1];
                    bl[nh * 2 + 1][0] = r[2]; bl[nh * 2 + 1][1] = r[3];
                }
            }
#pragma unroll
            for (int mg = 0; mg < 2; mg++)
#pragma unroll
                for (int ng = 0; ng < NG; ng++) {
                    mma16816(acc[mg][ng], ah[mg], bh[ng]);
                    if (S3) {
                        mma16816(acc[mg][ng], ah[mg], bl[ng]);
                        mma16816(acc[mg][ng], al[mg], bh[ng]);
                    }
                }
        }
    }

    // ------------------------------- epilogue ----------------------------
    int t4 = lane >> 2, t2 = (lane & 3) * 2;
#pragma unroll
    for (int mg = 0; mg < 2; mg++)
#pragma unroll
        for (int ng = 0; ng < NG; ng++) {
            float* c = acc[mg][ng];
            int col = n0 + wn * (NT / 4) + ng * 8 + t2;
#pragma unroll
            for (int hh = 0; hh < 2; hh++) {
                int row = m0 + wm * 32 + mg * 16 + t4 + hh * 8;
                float f0 = c[hh * 2], f1 = c[hh * 2 + 1];
                if (MODE == 2) {
                    __nv_bfloat16 h0 = __float2bfloat16(f0), h1 = __float2bfloat16(f1);
                    uint32_t hp = (uint32_t)__bfloat16_as_ushort(h0) |
                                  ((uint32_t)__bfloat16_as_ushort(h1) << 16);
                    uint32_t lp = pack2(f0 - __bfloat162float(h0), f1 - __bfloat162float(h1));
                    *(uint32_t*)&ShO[(size_t)row * KP + 1024 + col] = hp;
                    *(uint32_t*)&SlO[(size_t)row * KP + 1024 + col] = lp;
                } else {
                    float2 b2 = *(const float2*)&bias[col];
                    float v0 = f0 + b2.x, v1 = f1 + b2.y;
                    if (MODE == 1) {
                        float2 r2 = *(const float2*)&res[(size_t)row * DD + col];
                        v0 += r2.x; v1 += r2.y;
                    }
                    float2 o2 = {v0, v1};
                    *(float2*)&dst[(size_t)row * DD + col] = o2;
                    if (MODE == 1) {
                        __nv_bfloat16 h0 = __float2bfloat16(v0), h1 = __float2bfloat16(v1);
                        uint32_t hp = (uint32_t)__bfloat16_as_ushort(h0) |
                                      ((uint32_t)__bfloat16_as_ushort(h1) << 16);
                        uint32_t lp = pack2(v0 - __bfloat162float(h0), v1 - __bfloat162float(h1));
                        *(uint32_t*)&ShO[(size_t)row * KP + col] = hp;
                        *(uint32_t*)&SlO[(size_t)row * KP + col] = lp;
                    }
                }
            }
        }
}

// ------------------------------- launch ----------------------------------
extern "C" void kernel_launch(void* const* d_in, const int* in_sizes, int n_in,
                              void* d_out, int out_size) {
    const float* x   = (const float*)d_in[0];
    const int*   q   = (const int*)d_in[1];
    const float* sc  = (const float*)d_in[2];
    const float* bia = (const float*)d_in[3];
    const float* la  = (const float*)d_in[4];
    const float* lbw = (const float*)d_in[5];
    const float* gam = (const float*)d_in[6];
    const float* bet = (const float*)d_in[7];
    float* out = (float*)d_out;

    __nv_bfloat16 *Wh, *Wl, *La, *Sh[2], *Sl[2];
    float *H, *Y;
    cudaGetSymbolAddress((void**)&Wh, g_Wh);
    cudaGetSymbolAddress((void**)&Wl, g_Wl);
    cudaGetSymbolAddress((void**)&La, g_La);
    cudaGetSymbolAddress((void**)&Sh[0], g_Sh0);
    cudaGetSymbolAddress((void**)&Sl[0], g_Sl0);
    cudaGetSymbolAddress((void**)&Sh[1], g_Sh1);
    cudaGetSymbolAddress((void**)&Sl[1], g_Sl1);
    cudaGetSymbolAddress((void**)&H,  g_H);
    cudaGetSymbolAddress((void**)&Y,  g_Y);

    const int SM_MAIN = 1024 + 3 * 65536;   // 197632
    const int SM_LORA = 1024 + 3 * 24576;   // 74752
    cudaFuncSetAttribute(k_gemm<128, 17, true, 0>, cudaFuncAttributeMaxDynamicSharedMemorySize, SM_MAIN);
    cudaFuncSetAttribute(k_gemm<128, 17, true, 1>, cudaFuncAttributeMaxDynamicSharedMemorySize, SM_MAIN);
    cudaFuncSetAttribute(k_gemm<64, 16, false, 2>, cudaFuncAttributeMaxDynamicSharedMemorySize, SM_LORA);

    k_prepw<<<6 * DD * KP / 256, 256>>>(q, sc, lbw);
    k_prepla<<<6 * 64 * KP / 256, 256>>>(la);
    k_convert<<<MTOT * DD / 4 / 256, 256>>>(x);

    int p = 0;
    for (int blk = 0; blk < 3; ++blk) {
        int l0 = 2 * blk, l1 = 2 * blk + 1;
        k_gemm<64, 16, false, 2><<<dim3(1, MTOT / 128), 512, SM_LORA>>>(
            Sh[p], nullptr, La + (size_t)l0 * 64 * KP, nullptr,
            nullptr, nullptr, nullptr, Sh[p], Sl[p]);
        k_gemm<128, 17, true, 0><<<dim3(8, MTOT / 128), 512, SM_MAIN>>>(
            Sh[p], Sl[p], Wh + (size_t)l0 * DD * KP, Wl + (size_t)l0 * DD * KP,
            bia + l0 * DD, nullptr, Y, nullptr, nullptr);
        k_lngelu<<<MTOT / 8, 256>>>(Y, gam + blk * DD, bet + blk * DD, Sh[p], Sl[p]);
        k_gemm<64, 16, false, 2><<<dim3(1, MTOT / 128), 512, SM_LORA>>>(
            Sh[p], nullptr, La + (size_t)l1 * 64 * KP, nullptr,
            nullptr, nullptr, nullptr, Sh[p], Sl[p]);
        float* dst = (blk == 2) ? out : H;
        k_gemm<128, 17, true, 1><<<dim3(8, MTOT / 128), 512, SM_MAIN>>>(
            Sh[p], Sl[p], Wh + (size_t)l1 * DD * KP, Wl + (size_t)l1 * DD * KP,
            bia + l1 * DD, H, dst, Sh[p ^ 1], Sl[p ^ 1]);
        p ^= 1;
    }
}

// round 9
// speedup vs baseline: 2.9120x; 1.0576x over previous
#include <cuda_runtime.h>
#include <cuda_bf16.h>
#include <math.h>
#include <stdint.h>

#define MTOT 32768
#define DD   1024
#define KP   1088
#define RR   32

// ---------------- device scratch (no allocations allowed) ----------------
__device__ __align__(1024) __nv_bfloat16 g_Sh0[MTOT * KP];
__device__ __align__(1024) __nv_bfloat16 g_Sl0[MTOT * KP];
__device__ __align__(1024) __nv_bfloat16 g_Sh1[MTOT * KP];
__device__ __align__(1024) __nv_bfloat16 g_Sl1[MTOT * KP];
__device__ __align__(1024) __nv_bfloat16 g_Wh[6 * DD * KP];
__device__ __align__(1024) __nv_bfloat16 g_Wl[6 * DD * KP];
__device__ __align__(1024) __nv_bfloat16 g_La[6 * 64 * KP];
__device__ float g_H[MTOT * DD];
__device__ float g_Y[MTOT * DD];

// ------------------------------ helpers ----------------------------------
__device__ __forceinline__ uint32_t s2u(const void* p) {
    uint32_t a;
    asm("{ .reg .u64 t; cvta.to.shared.u64 t, %1; cvt.u32.u64 %0, t; }" : "=r"(a) : "l"(p));
    return a;
}
__device__ __forceinline__ void cpa(uint32_t s, const void* g) {
    asm volatile("cp.async.cg.shared.global [%0], [%1], 16;" :: "r"(s), "l"(g) : "memory");
}
__device__ __forceinline__ void ldsm4(uint32_t* r, uint32_t a) {
    asm volatile("ldmatrix.sync.aligned.m8n8.x4.shared.b16 {%0,%1,%2,%3}, [%4];"
                 : "=r"(r[0]), "=r"(r[1]), "=r"(r[2]), "=r"(r[3]) : "r"(a));
}
__device__ __forceinline__ void mma16816(float* c, const uint32_t* a, const uint32_t* b) {
    asm volatile(
        "mma.sync.aligned.m16n8k16.row.col.f32.bf16.bf16.f32 "
        "{%0,%1,%2,%3}, {%4,%5,%6,%7}, {%8,%9}, {%0,%1,%2,%3};"
        : "+f"(c[0]), "+f"(c[1]), "+f"(c[2]), "+f"(c[3])
        : "r"(a[0]), "r"(a[1]), "r"(a[2]), "r"(a[3]), "r"(b[0]), "r"(b[1]));
}
__device__ __forceinline__ uint32_t pack2(float a, float b) {
    __nv_bfloat16 x = __float2bfloat16(a), y = __float2bfloat16(b);
    return (uint32_t)__bfloat16_as_ushort(x) | ((uint32_t)__bfloat16_as_ushort(y) << 16);
}
__device__ __forceinline__ uint32_t swz(uint32_t o) { return o ^ ((o >> 3) & 0x70); }

// ------------------- prep: dequant + split weights (+lb concat) ----------
__global__ void k_prepw(const int* __restrict__ q, const float* __restrict__ s,
                        const float* __restrict__ lb) {
    int idx = blockIdx.x * 256 + threadIdx.x;
    int i = idx % KP, row = idx / KP;   // row = l*DD + o
    float w;
    if (i < 1024)      w = ((float)q[row * DD + i] * (1.0f / 7.5f) - 1.0f) * s[row * 64 + (i >> 4)];
    else if (i < 1056) w = lb[row * RR + (i - 1024)];
    else               w = 0.0f;
    __nv_bfloat16 hi = __float2bfloat16(w);
    g_Wh[idx] = hi;
    g_Wl[idx] = __float2bfloat16(w - __bfloat162float(hi));
}
__global__ void k_prepla(const float* __restrict__ la) {
    int idx = blockIdx.x * 256 + threadIdx.x;
    int i = idx % KP, rem = idx / KP;
    int r = rem % 64, l = rem / 64;
    float v = (r < RR && i < 1024) ? la[(l * RR + r) * DD + i] : 0.0f;
    g_La[idx] = __float2bfloat16(v);
}
// x -> g_H (fp32) + splits into buffer 0
__global__ void k_convert(const float* __restrict__ X) {
    int t = blockIdx.x * 256 + threadIdx.x;
    int m = t >> 8, c4 = (t & 255) * 4;
    float4 v = ((const float4*)X)[t];
    ((float4*)g_H)[t] = v;
    float h0 = __bfloat162float(__float2bfloat16(v.x));
    float h1 = __bfloat162float(__float2bfloat16(v.y));
    float h2 = __bfloat162float(__float2bfloat16(v.z));
    float h3 = __bfloat162float(__float2bfloat16(v.w));
    uint2 uh = {pack2(v.x, v.y), pack2(v.z, v.w)};
    uint2 ul = {pack2(v.x - h0, v.y - h1), pack2(v.z - h2, v.w - h3)};
    *(uint2*)&g_Sh0[(size_t)m * KP + c4] = uh;
    *(uint2*)&g_Sl0[(size_t)m * KP + c4] = ul;
}

// ---------------- LayerNorm + exact GELU -> splits -----------------------
__global__ void __launch_bounds__(256) k_lngelu(const float* __restrict__ Y,
                                                const float* __restrict__ g,
                                                const float* __restrict__ b,
                                                __nv_bfloat16* __restrict__ oh,
                                                __nv_bfloat16* __restrict__ ol) {
    int warp = threadIdx.x >> 5, lane = threadIdx.x & 31;
    int t = blockIdx.x * 8 + warp;
    const float4* row = (const float4*)(Y + (size_t)t * DD);
    float4 v[8];
    float s = 0.f, sq = 0.f;
#pragma unroll
    for (int i = 0; i < 8; i++) {
        v[i] = row[i * 32 + lane];
        s  += v[i].x + v[i].y + v[i].z + v[i].w;
        sq += v[i].x * v[i].x + v[i].y * v[i].y + v[i].z * v[i].z + v[i].w * v[i].w;
    }
#pragma unroll
    for (int o = 16; o > 0; o >>= 1) {
        s  += __shfl_xor_sync(0xffffffffu, s, o);
        sq += __shfl_xor_sync(0xffffffffu, sq, o);
    }
    float mu  = s * (1.f / 1024.f);
    float var = sq * (1.f / 1024.f) - mu * mu;
    float rs  = rsqrtf(var + 1e-5f);
#pragma unroll
    for (int i = 0; i < 8; i++) {
        int c4 = (i * 32 + lane) * 4;
        float xv[4] = {v[i].x, v[i].y, v[i].z, v[i].w};
        float yv[4];
#pragma unroll
        for (int j = 0; j < 4; j++) {
            float xn = (xv[j] - mu) * rs * g[c4 + j] + b[c4 + j];
            yv[j] = 0.5f * xn * (1.f + erff(xn * 0.70710678118654752f));
        }
        float h0 = __bfloat162float(__float2bfloat16(yv[0]));
        float h1 = __bfloat162float(__float2bfloat16(yv[1]));
        float h2 = __bfloat162float(__float2bfloat16(yv[2]));
        float h3 = __bfloat162float(__float2bfloat16(yv[3]));
        uint2 uh = {pack2(yv[0], yv[1]), pack2(yv[2], yv[3])};
        uint2 ul = {pack2(yv[0] - h0, yv[1] - h1), pack2(yv[2] - h2, yv[3] - h3)};
        *(uint2*)&oh[(size_t)t * KP + c4] = uh;
        *(uint2*)&ol[(size_t)t * KP + c4] = ul;
    }
}

// ----------- MAIN GEMM: 256 thr, CTA 128x256, warp 64x64, 2-stage --------
// D = A[128,K] @ B[256,K]^T, 3-term bf16 split, fp32 accum.
// MODE 0: dst = D + bias ; MODE 1: dst = D + bias + res, splits -> ShO/SlO
template <int MODE>
__global__ void __launch_bounds__(256, 1) k_gmain(
    const __nv_bfloat16* __restrict__ Ah_g, const __nv_bfloat16* __restrict__ Al_g,
    const __nv_bfloat16* __restrict__ Bh_g, const __nv_bfloat16* __restrict__ Bl_g,
    const float* __restrict__ bias, const float* __restrict__ res,
    float* __restrict__ dst,
    __nv_bfloat16* __restrict__ ShO, __nv_bfloat16* __restrict__ SlO)
{
    constexpr int NKT   = 17;
    constexpr int OF_AL = 16384;
    constexpr int OF_BH = 32768;
    constexpr int OF_BL = 65536;
    constexpr int STG   = 98304;

    extern __shared__ char smem[];
    uint32_t ab = (s2u(smem) + 1023u) & ~1023u;

    int tid = threadIdx.x, wid = tid >> 5, lane = tid & 31;
    int n0 = blockIdx.x * 256;
    int m0 = blockIdx.y * 128;
    int wm = wid & 1, wn = wid >> 1;                    // 2 x 4 warps, 64x64 tiles

    auto ldst = [&](int kt, int s) {
        uint32_t base = ab + s * STG;
        size_t kb = (size_t)kt * 128;
        const char* pAh = (const char*)Ah_g + (size_t)m0 * (KP * 2) + kb;
        const char* pAl = (const char*)Al_g + (size_t)m0 * (KP * 2) + kb;
        const char* pBh = (const char*)Bh_g + (size_t)n0 * (KP * 2) + kb;
        const char* pBl = (const char*)Bl_g + (size_t)n0 * (KP * 2) + kb;
#pragma unroll
        for (int j = 0; j < 4; j++) {                   // A: 128 rows x 8 chunks
            int c = j * 256 + tid, row = c >> 3, qq = c & 7;
            uint32_t off = swz((uint32_t)(row * 128 + qq * 16));
            cpa(base + off, pAh + (size_t)row * (KP * 2) + qq * 16);
            cpa(base + OF_AL + off, pAl + (size_t)row * (KP * 2) + qq * 16);
        }
#pragma unroll
        for (int j = 0; j < 8; j++) {                   // B: 256 rows x 8 chunks
            int c = j * 256 + tid, row = c >> 3, qq = c & 7;
            uint32_t off = swz((uint32_t)(row * 128 + qq * 16));
            cpa(base + OF_BH + off, pBh + (size_t)row * (KP * 2) + qq * 16);
            cpa(base + OF_BL + off, pBl + (size_t)row * (KP * 2) + qq * 16);
        }
        asm volatile("cp.async.commit_group;" ::: "memory");
    };

    float acc[4][8][4];
#pragma unroll
    for (int i = 0; i < 4; i++)
#pragma unroll
        for (int j = 0; j < 8; j++)
#pragma unroll
            for (int q = 0; q < 4; q++) acc[i][j][q] = 0.f;

    ldst(0, 0);

    for (int k = 0; k < NKT; k++) {
        const int s = k & 1;
        asm volatile("cp.async.wait_group 0;" ::: "memory");
        __syncthreads();
        if (k + 1 < NKT) ldst(k + 1, s ^ 1);
        uint32_t aB = ab + s * STG;
        uint32_t bB = aB + OF_BH;
#pragma unroll
        for (int kc = 0; kc < 4; kc++) {
            uint32_t bh[8][2], bl[8][2];
            uint32_t nbyte = (uint32_t)(kc * 32 + (((lane >> 3) & 1) << 4));
#pragma unroll
            for (int nh = 0; nh < 4; nh++) {
                uint32_t nrow = (uint32_t)(wn * 64 + nh * 16 + ((lane >> 4) << 3) + (lane & 7));
                uint32_t off = swz(nrow * 128 + nbyte);
                uint32_t r[4];
                ldsm4(r, bB + off);
                bh[nh * 2][0] = r[0]; bh[nh * 2][1] = r[1];
                bh[nh * 2 + 1][0] = r[2]; bh[nh * 2 + 1][1] = r[3];
                ldsm4(r, aB + OF_BL + off);
                bl[nh * 2][0] = r[0]; bl[nh * 2][1] = r[1];
                bl[nh * 2 + 1][0] = r[2]; bl[nh * 2 + 1][1] = r[3];
            }
            uint32_t abyte = (uint32_t)(kc * 32 + ((lane >> 4) << 4));
#pragma unroll
            for (int mg = 0; mg < 4; mg++) {
                uint32_t ah[4], al[4];
                uint32_t off = swz((uint32_t)((wm * 64 + mg * 16 + (lane & 15)) * 128) + abyte);
                ldsm4(ah, aB + off);
                ldsm4(al, aB + OF_AL + off);
#pragma unroll
                for (int ng = 0; ng < 8; ng++) {
                    mma16816(acc[mg][ng], ah, bh[ng]);
                    mma16816(acc[mg][ng], ah, bl[ng]);
                    mma16816(acc[mg][ng], al, bh[ng]);
                }
            }
        }
    }

    // ------------------------------- epilogue ----------------------------
    int t4 = lane >> 2, t2 = (lane & 3) * 2;
#pragma unroll
    for (int mg = 0; mg < 4; mg++)
#pragma unroll
        for (int ng = 0; ng < 8; ng++) {
            float* c = acc[mg][ng];
            int col = n0 + wn * 64 + ng * 8 + t2;
#pragma unroll
            for (int hh = 0; hh < 2; hh++) {
                int row = m0 + wm * 64 + mg * 16 + t4 + hh * 8;
                float2 b2 = *(const float2*)&bias[col];
                float v0 = c[hh * 2] + b2.x, v1 = c[hh * 2 + 1] + b2.y;
                if (MODE == 1) {
                    float2 r2 = *(const float2*)&res[(size_t)row * DD + col];
                    v0 += r2.x; v1 += r2.y;
                }
                float2 o2 = {v0, v1};
                *(float2*)&dst[(size_t)row * DD + col] = o2;
                if (MODE == 1) {
                    __nv_bfloat16 h0 = __float2bfloat16(v0), h1 = __float2bfloat16(v1);
                    uint32_t hp = (uint32_t)__bfloat16_as_ushort(h0) |
                                  ((uint32_t)__bfloat16_as_ushort(h1) << 16);
                    uint32_t lp = pack2(v0 - __bfloat162float(h0), v1 - __bfloat162float(h1));
                    *(uint32_t*)&ShO[(size_t)row * KP + col] = hp;
                    *(uint32_t*)&SlO[(size_t)row * KP + col] = lp;
                }
            }
        }
}

// ------------- LoRA-U GEMM: 512 thr, 128x64, 3-stage (unchanged) ---------
// U = X @ la^T, bf16 single pass; writes bf16 hi/lo to S cols [1024..1088)
__global__ void __launch_bounds__(512, 1) k_loraU(
    const __nv_bfloat16* __restrict__ Ah_g, const __nv_bfloat16* __restrict__ Bh_g,
    __nv_bfloat16* __restrict__ ShO, __nv_bfloat16* __restrict__ SlO)
{
    constexpr int NKT = 16;
    constexpr int OF_BH = 16384;
    constexpr int STG = 24576;
    extern __shared__ char smem[];
    uint32_t ab = (s2u(smem) + 1023u) & ~1023u;
    int tid = threadIdx.x, wid = tid >> 5, lane = tid & 31;
    int m0 = blockIdx.y * 128;
    int wm = wid & 3, wn = wid >> 2;

    auto ldst = [&](int kt, int s) {
        uint32_t base = ab + s * STG;
        size_t kb = (size_t)kt * 128;
        const char* pAh = (const char*)Ah_g + (size_t)m0 * (KP * 2) + kb;
        const char* pBh = (const char*)Bh_g + kb;
#pragma unroll
        for (int j = 0; j < 2; j++) {
            int c = j * 512 + tid, row = c >> 3, qq = c & 7;
            uint32_t off = swz((uint32_t)(row * 128 + qq * 16));
            cpa(base + off, pAh + (size_t)row * (KP * 2) + qq * 16);
        }
        {
            int c = tid, row = c >> 3, qq = c & 7;
            uint32_t off = swz((uint32_t)(row * 128 + qq * 16));
            cpa(base + OF_BH + off, pBh + (size_t)row * (KP * 2) + qq * 16);
        }
        asm volatile("cp.async.commit_group;" ::: "memory");
    };

    float acc[2][2][4];
#pragma unroll
    for (int i = 0; i < 2; i++)
#pragma unroll
        for (int j = 0; j < 2; j++)
#pragma unroll
            for (int q = 0; q < 4; q++) acc[i][j][q] = 0.f;

    ldst(0, 0); ldst(1, 1);
    for (int k = 0; k < NKT; k++) {
        const int s = k % 3;
        asm volatile("cp.async.wait_group 1;" ::: "memory");
        __syncthreads();
        if (k + 2 < NKT) ldst(k + 2, (k + 2) % 3);
        uint32_t aB = ab + s * STG;
        uint32_t bB = aB + OF_BH;
#pragma unroll
        for (int kc = 0; kc < 4; kc++) {
            uint32_t ah[2][4], bh[2][2];
            uint32_t abyte = (uint32_t)(kc * 32 + ((lane >> 4) << 4));
#pragma unroll
            for (int mg = 0; mg < 2; mg++) {
                uint32_t off = swz((uint32_t)((wm * 32 + mg * 16 + (lane & 15)) * 128) + abyte);
                ldsm4(ah[mg], aB + off);
            }
            uint32_t nbyte = (uint32_t)(kc * 32 + (((lane >> 3) & 1) << 4));
            {
                uint32_t nrow = (uint32_t)(wn * 16 + ((lane >> 4) << 3) + (lane & 7));
                uint32_t off = swz(nrow * 128 + nbyte);
                uint32_t r[4];
                ldsm4(r, bB + off);
                bh[0][0] = r[0]; bh[0][1] = r[1];
                bh[1][0] = r[2]; bh[1][1] = r[3];
            }
#pragma unroll
            for (int mg = 0; mg < 2; mg++)
#pragma unroll
                for (int ng = 0; ng < 2; ng++)
                    mma16816(acc[mg][ng], ah[mg], bh[ng]);
        }
    }
    int t4 = lane >> 2, t2 = (lane & 3) * 2;
#pragma unroll
    for (int mg = 0; mg < 2; mg++)
#pragma unroll
        for (int ng = 0; ng < 2; ng++) {
            float* c = acc[mg][ng];
            int col = wn * 16 + ng * 8 + t2;
#pragma unroll
            for (int hh = 0; hh < 2; hh++) {
                int row = m0 + wm * 32 + mg * 16 + t4 + hh * 8;
                float f0 = c[hh * 2], f1 = c[hh * 2 + 1];
                __nv_bfloat16 h0 = __float2bfloat16(f0), h1 = __float2bfloat16(f1);
                uint32_t hp = (uint32_t)__bfloat16_as_ushort(h0) |
                              ((uint32_t)__bfloat16_as_ushort(h1) << 16);
                uint32_t lp = pack2(f0 - __bfloat162float(h0), f1 - __bfloat162float(h1));
                *(uint32_t*)&ShO[(size_t)row * KP + 1024 + col] = hp;
                *(uint32_t*)&SlO[(size_t)row * KP + 1024 + col] = lp;
            }
        }
}

// ------------------------------- launch ----------------------------------
extern "C" void kernel_launch(void* const* d_in, const int* in_sizes, int n_in,
                              void* d_out, int out_size) {
    const float* x   = (const float*)d_in[0];
    const int*   q   = (const int*)d_in[1];
    const float* sc  = (const float*)d_in[2];
    const float* bia = (const float*)d_in[3];
    const float* la  = (const float*)d_in[4];
    const float* lbw = (const float*)d_in[5];
    const float* gam = (const float*)d_in[6];
    const float* bet = (const float*)d_in[7];
    float* out = (float*)d_out;

    __nv_bfloat16 *Wh, *Wl, *La, *Sh[2], *Sl[2];
    float *H, *Y;
    cudaGetSymbolAddress((void**)&Wh, g_Wh);
    cudaGetSymbolAddress((void**)&Wl, g_Wl);
    cudaGetSymbolAddress((void**)&La, g_La);
    cudaGetSymbolAddress((void**)&Sh[0], g_Sh0);
    cudaGetSymbolAddress((void**)&Sl[0], g_Sl0);
    cudaGetSymbolAddress((void**)&Sh[1], g_Sh1);
    cudaGetSymbolAddress((void**)&Sl[1], g_Sl1);
    cudaGetSymbolAddress((void**)&H,  g_H);
    cudaGetSymbolAddress((void**)&Y,  g_Y);

    const int SM_MAIN = 1024 + 2 * 98304;   // 197632
    const int SM_LORA = 1024 + 3 * 24576;   // 74752
    cudaFuncSetAttribute(k_gmain<0>, cudaFuncAttributeMaxDynamicSharedMemorySize, SM_MAIN);
    cudaFuncSetAttribute(k_gmain<1>, cudaFuncAttributeMaxDynamicSharedMemorySize, SM_MAIN);
    cudaFuncSetAttribute(k_loraU, cudaFuncAttributeMaxDynamicSharedMemorySize, SM_LORA);

    k_prepw<<<6 * DD * KP / 256, 256>>>(q, sc, lbw);
    k_prepla<<<6 * 64 * KP / 256, 256>>>(la);
    k_convert<<<MTOT * DD / 4 / 256, 256>>>(x);

    int p = 0;
    for (int blk = 0; blk < 3; ++blk) {
        int l0 = 2 * blk, l1 = 2 * blk + 1;
        k_loraU<<<dim3(1, MTOT / 128), 512, SM_LORA>>>(
            Sh[p], La + (size_t)l0 * 64 * KP, Sh[p], Sl[p]);
        k_gmain<0><<<dim3(4, MTOT / 128), 256, SM_MAIN>>>(
            Sh[p], Sl[p], Wh + (size_t)l0 * DD * KP, Wl + (size_t)l0 * DD * KP,
            bia + l0 * DD, nullptr, Y, nullptr, nullptr);
        k_lngelu<<<MTOT / 8, 256>>>(Y, gam + blk * DD, bet + blk * DD, Sh[p], Sl[p]);
        k_loraU<<<dim3(1, MTOT / 128), 512, SM_LORA>>>(
            Sh[p], La + (size_t)l1 * 64 * KP, Sh[p], Sl[p]);
        float* dst = (blk == 2) ? out : H;
        k_gmain<1><<<dim3(4, MTOT / 128), 256, SM_MAIN>>>(
            Sh[p], Sl[p], Wh + (size_t)l1 * DD * KP, Wl + (size_t)l1 * DD * KP,
            bia + l1 * DD, H, dst, Sh[p ^ 1], Sl[p ^ 1]);
        p ^= 1;
    }
}

// round 10
// speedup vs baseline: 3.2175x; 1.1049x over previous
#include <cuda_runtime.h>
#include <cuda_fp16.h>
#include <math.h>
#include <stdint.h>

#define MTOT 32768
#define DD   1024

// ---------------- device scratch (no allocations allowed) ----------------
__device__ __align__(1024) __half g_Sh0[MTOT * DD];
__device__ __align__(1024) __half g_Sl0[MTOT * DD];
__device__ __align__(1024) __half g_Sh1[MTOT * DD];
__device__ __align__(1024) __half g_Sl1[MTOT * DD];
__device__ __align__(1024) __half g_Wh[6 * DD * DD];
__device__ __align__(1024) __half g_Wl[6 * DD * DD];
__device__ float g_H[MTOT * DD];
__device__ float g_Y[MTOT * DD];   // also reused as lb@la scratch (first 6M floats) during prep

// ------------------------------ helpers ----------------------------------
__device__ __forceinline__ uint32_t s2u(const void* p) {
    uint32_t a;
    asm("{ .reg .u64 t; cvta.to.shared.u64 t, %1; cvt.u32.u64 %0, t; }" : "=r"(a) : "l"(p));
    return a;
}
__device__ __forceinline__ void cpa(uint32_t s, const void* g) {
    asm volatile("cp.async.cg.shared.global [%0], [%1], 16;" :: "r"(s), "l"(g) : "memory");
}
__device__ __forceinline__ void ldsm4(uint32_t* r, uint32_t a) {
    asm volatile("ldmatrix.sync.aligned.m8n8.x4.shared.b16 {%0,%1,%2,%3}, [%4];"
                 : "=r"(r[0]), "=r"(r[1]), "=r"(r[2]), "=r"(r[3]) : "r"(a));
}
__device__ __forceinline__ void mma16816(float* c, const uint32_t* a, const uint32_t* b) {
    asm volatile(
        "mma.sync.aligned.m16n8k16.row.col.f32.f16.f16.f32 "
        "{%0,%1,%2,%3}, {%4,%5,%6,%7}, {%8,%9}, {%0,%1,%2,%3};"
        : "+f"(c[0]), "+f"(c[1]), "+f"(c[2]), "+f"(c[3])
        : "r"(a[0]), "r"(a[1]), "r"(a[2]), "r"(a[3]), "r"(b[0]), "r"(b[1]));
}
__device__ __forceinline__ uint32_t h2u(float a, float b) {
    __half2 h = __floats2half2_rn(a, b);
    return *(uint32_t*)&h;
}
__device__ __forceinline__ float hres(float a) {   // residual after fp16 rounding
    return a - __half2float(__float2half_rn(a));
}
__device__ __forceinline__ uint32_t swz(uint32_t o) { return o ^ ((o >> 3) & 0x70); }

// ---------------- prep 1: M = lb @ la  (rank-32 outer product) -----------
// grid = 6*64 blocks (one block = one layer, 16 output rows), 256 threads.
// smem: sla[32][1024] fp32 (128KB) + slb[16][32] fp32.
__global__ void __launch_bounds__(256) k_loramm(const float* __restrict__ lb,
                                                const float* __restrict__ la,
                                                float* __restrict__ M) {
    extern __shared__ float sm[];
    float* sla = sm;                 // 32*1024
    float* slb = sm + 32 * 1024;     // 16*32
    int l = blockIdx.x >> 6, ot = blockIdx.x & 63;
    const float* laL = la + (size_t)l * 32 * 1024;
    const float* lbL = lb + (size_t)l * 1024 * 32 + ot * 16 * 32;
    for (int i = threadIdx.x; i < 32 * 1024 / 4; i += 256)
        ((float4*)sla)[i] = ((const float4*)laL)[i];
    for (int i = threadIdx.x; i < 16 * 32 / 4; i += 256)
        ((float4*)slb)[i] = ((const float4*)lbL)[i];
    __syncthreads();
    float acc[16][4];
#pragma unroll
    for (int o = 0; o < 16; o++)
#pragma unroll
        for (int j = 0; j < 4; j++) acc[o][j] = 0.f;
    int i0 = threadIdx.x * 4;
#pragma unroll
    for (int r = 0; r < 32; r++) {
        float4 la4 = *(float4*)&sla[r * 1024 + i0];
#pragma unroll
        for (int o = 0; o < 16; o++) {
            float b = slb[o * 32 + r];
            acc[o][0] += b * la4.x; acc[o][1] += b * la4.y;
            acc[o][2] += b * la4.z; acc[o][3] += b * la4.w;
        }
    }
#pragma unroll
    for (int o = 0; o < 16; o++) {
        float4 v = {acc[o][0], acc[o][1], acc[o][2], acc[o][3]};
        *(float4*)&M[((size_t)l * 1024 + ot * 16 + o) * 1024 + i0] = v;
    }
}

// ---------------- prep 2: dequant + lora fold -> fp16 hi/lo --------------
__global__ void k_prepw(const int* __restrict__ q, const float* __restrict__ s,
                        const float* __restrict__ M) {
    int idx = blockIdx.x * 256 + threadIdx.x;     // over 6*1024*1024
    int i = idx & 1023, row = idx >> 10;          // row = l*1024 + o
    float w = ((float)q[idx] * (1.0f / 7.5f) - 1.0f) * s[(size_t)row * 64 + (i >> 4)]
            + M[idx];
    g_Wh[idx] = __float2half_rn(w);
    g_Wl[idx] = __float2half_rn(hres(w));
}

// x -> g_H (fp32) + fp16 splits into buffer 0
__global__ void k_convert(const float* __restrict__ X) {
    int t = blockIdx.x * 256 + threadIdx.x;
    int m = t >> 8, c4 = (t & 255) * 4;
    float4 v = ((const float4*)X)[t];
    ((float4*)g_H)[t] = v;
    uint2 uh = {h2u(v.x, v.y), h2u(v.z, v.w)};
    uint2 ul = {h2u(hres(v.x), hres(v.y)), h2u(hres(v.z), hres(v.w))};
    *(uint2*)&g_Sh0[(size_t)m * DD + c4] = uh;
    *(uint2*)&g_Sl0[(size_t)m * DD + c4] = ul;
}

// ---------------- LayerNorm + exact GELU -> fp16 splits ------------------
__global__ void __launch_bounds__(256) k_lngelu(const float* __restrict__ Y,
                                                const float* __restrict__ g,
                                                const float* __restrict__ b,
                                                __half* __restrict__ oh,
                                                __half* __restrict__ ol) {
    int warp = threadIdx.x >> 5, lane = threadIdx.x & 31;
    int t = blockIdx.x * 8 + warp;
    const float4* row = (const float4*)(Y + (size_t)t * DD);
    float4 v[8];
    float s = 0.f, sq = 0.f;
#pragma unroll
    for (int i = 0; i < 8; i++) {
        v[i] = row[i * 32 + lane];
        s  += v[i].x + v[i].y + v[i].z + v[i].w;
        sq += v[i].x * v[i].x + v[i].y * v[i].y + v[i].z * v[i].z + v[i].w * v[i].w;
    }
#pragma unroll
    for (int o = 16; o > 0; o >>= 1) {
        s  += __shfl_xor_sync(0xffffffffu, s, o);
        sq += __shfl_xor_sync(0xffffffffu, sq, o);
    }
    float mu  = s * (1.f / 1024.f);
    float var = sq * (1.f / 1024.f) - mu * mu;
    float rs  = rsqrtf(var + 1e-5f);
#pragma unroll
    for (int i = 0; i < 8; i++) {
        int c4 = (i * 32 + lane) * 4;
        float xv[4] = {v[i].x, v[i].y, v[i].z, v[i].w};
        float yv[4];
#pragma unroll
        for (int j = 0; j < 4; j++) {
            float xn = (xv[j] - mu) * rs * g[c4 + j] + b[c4 + j];
            yv[j] = 0.5f * xn * (1.f + erff(xn * 0.70710678118654752f));
        }
        uint2 uh = {h2u(yv[0], yv[1]), h2u(yv[2], yv[3])};
        uint2 ul = {h2u(hres(yv[0]), hres(yv[1])), h2u(hres(yv[2]), hres(yv[3]))};
        *(uint2*)&oh[(size_t)t * DD + c4] = uh;
        *(uint2*)&ol[(size_t)t * DD + c4] = ul;
    }
}

// ----------- MAIN GEMM: 256 thr, CTA 128x256, warp 64x64, 2-stage --------
// D = A[128,1024] @ B[256,1024]^T, 3-term fp16 split, fp32 accum.
// MODE 0: dst = D + bias ; MODE 1: dst = D + bias + res, splits -> ShO/SlO
template <int MODE>
__global__ void __launch_bounds__(256, 1) k_gmain(
    const __half* __restrict__ Ah_g, const __half* __restrict__ Al_g,
    const __half* __restrict__ Bh_g, const __half* __restrict__ Bl_g,
    const float* __restrict__ bias, const float* __restrict__ res,
    float* __restrict__ dst,
    __half* __restrict__ ShO, __half* __restrict__ SlO)
{
    constexpr int NKT   = 16;           // 16 x 64-element k-tiles = K 1024
    constexpr int OF_AL = 16384;
    constexpr int OF_BH = 32768;
    constexpr int OF_BL = 65536;
    constexpr int STG   = 98304;
    constexpr int RB    = DD * 2;       // row bytes

    extern __shared__ char smem[];
    uint32_t ab = (s2u(smem) + 1023u) & ~1023u;

    int tid = threadIdx.x, wid = tid >> 5, lane = tid & 31;
    int n0 = blockIdx.x * 256;
    int m0 = blockIdx.y * 128;
    int wm = wid & 1, wn = wid >> 1;                    // 2 x 4 warps, 64x64 tiles

    auto ldst = [&](int kt, int s) {
        uint32_t base = ab + s * STG;
        size_t kb = (size_t)kt * 128;
        const char* pAh = (const char*)Ah_g + (size_t)m0 * RB + kb;
        const char* pAl = (const char*)Al_g + (size_t)m0 * RB + kb;
        const char* pBh = (const char*)Bh_g + (size_t)n0 * RB + kb;
        const char* pBl = (const char*)Bl_g + (size_t)n0 * RB + kb;
#pragma unroll
        for (int j = 0; j < 4; j++) {                   // A: 128 rows x 8 chunks
            int c = j * 256 + tid, row = c >> 3, qq = c & 7;
            uint32_t off = swz((uint32_t)(row * 128 + qq * 16));
            cpa(base + off, pAh + (size_t)row * RB + qq * 16);
            cpa(base + OF_AL + off, pAl + (size_t)row * RB + qq * 16);
        }
#pragma unroll
        for (int j = 0; j < 8; j++) {                   // B: 256 rows x 8 chunks
            int c = j * 256 + tid, row = c >> 3, qq = c & 7;
            uint32_t off = swz((uint32_t)(row * 128 + qq * 16));
            cpa(base + OF_BH + off, pBh + (size_t)row * RB + qq * 16);
            cpa(base + OF_BL + off, pBl + (size_t)row * RB + qq * 16);
        }
        asm volatile("cp.async.commit_group;" ::: "memory");
    };

    float acc[4][8][4];
#pragma unroll
    for (int i = 0; i < 4; i++)
#pragma unroll
        for (int j = 0; j < 8; j++)
#pragma unroll
            for (int q = 0; q < 4; q++) acc[i][j][q] = 0.f;

    ldst(0, 0);

    for (int k = 0; k < NKT; k++) {
        const int s = k & 1;
        asm volatile("cp.async.wait_group 0;" ::: "memory");
        __syncthreads();
        if (k + 1 < NKT) ldst(k + 1, s ^ 1);
        uint32_t aB = ab + s * STG;
        uint32_t bB = aB + OF_BH;
#pragma unroll
        for (int kc = 0; kc < 4; kc++) {
            uint32_t bh[8][2], bl[8][2];
            uint32_t nbyte = (uint32_t)(kc * 32 + (((lane >> 3) & 1) << 4));
#pragma unroll
            for (int nh = 0; nh < 4; nh++) {
                uint32_t nrow = (uint32_t)(wn * 64 + nh * 16 + ((lane >> 4) << 3) + (lane & 7));
                uint32_t off = swz(nrow * 128 + nbyte);
                uint32_t r[4];
                ldsm4(r, bB + off);
                bh[nh * 2][0] = r[0]; bh[nh * 2][1] = r[1];
                bh[nh * 2 + 1][0] = r[2]; bh[nh * 2 + 1][1] = r[3];
                ldsm4(r, aB + OF_BL + off);
                bl[nh * 2][0] = r[0]; bl[nh * 2][1] = r[1];
                bl[nh * 2 + 1][0] = r[2]; bl[nh * 2 + 1][1] = r[3];
            }
            uint32_t abyte = (uint32_t)(kc * 32 + ((lane >> 4) << 4));
#pragma unroll
            for (int mg = 0; mg < 4; mg++) {
                uint32_t ah[4], al[4];
                uint32_t off = swz((uint32_t)((wm * 64 + mg * 16 + (lane & 15)) * 128) + abyte);
                ldsm4(ah, aB + off);
                ldsm4(al, aB + OF_AL + off);
#pragma unroll
                for (int ng = 0; ng < 8; ng++) {
                    mma16816(acc[mg][ng], ah, bh[ng]);
                    mma16816(acc[mg][ng], ah, bl[ng]);
                    mma16816(acc[mg][ng], al, bh[ng]);
                }
            }
        }
    }

    // ------------------------------- epilogue ----------------------------
    int t4 = lane >> 2, t2 = (lane & 3) * 2;
#pragma unroll
    for (int mg = 0; mg < 4; mg++)
#pragma unroll
        for (int ng = 0; ng < 8; ng++) {
            float* c = acc[mg][ng];
            int col = n0 + wn * 64 + ng * 8 + t2;
#pragma unroll
            for (int hh = 0; hh < 2; hh++) {
                int row = m0 + wm * 64 + mg * 16 + t4 + hh * 8;
                float2 b2 = *(const float2*)&bias[col];
                float v0 = c[hh * 2] + b2.x, v1 = c[hh * 2 + 1] + b2.y;
                if (MODE == 1) {
                    float2 r2 = *(const float2*)&res[(size_t)row * DD + col];
                    v0 += r2.x; v1 += r2.y;
                }
                float2 o2 = {v0, v1};
                *(float2*)&dst[(size_t)row * DD + col] = o2;
                if (MODE == 1) {
                    *(uint32_t*)&ShO[(size_t)row * DD + col] = h2u(v0, v1);
                    *(uint32_t*)&SlO[(size_t)row * DD + col] = h2u(hres(v0), hres(v1));
                }
            }
        }
}

// ------------------------------- launch ----------------------------------
extern "C" void kernel_launch(void* const* d_in, const int* in_sizes, int n_in,
                              void* d_out, int out_size) {
    const float* x   = (const float*)d_in[0];
    const int*   q   = (const int*)d_in[1];
    const float* sc  = (const float*)d_in[2];
    const float* bia = (const float*)d_in[3];
    const float* la  = (const float*)d_in[4];
    const float* lbw = (const float*)d_in[5];
    const float* gam = (const float*)d_in[6];
    const float* bet = (const float*)d_in[7];
    float* out = (float*)d_out;

    __half *Wh, *Wl, *Sh[2], *Sl[2];
    float *H, *Y;
    cudaGetSymbolAddress((void**)&Wh, g_Wh);
    cudaGetSymbolAddress((void**)&Wl, g_Wl);
    cudaGetSymbolAddress((void**)&Sh[0], g_Sh0);
    cudaGetSymbolAddress((void**)&Sl[0], g_Sl0);
    cudaGetSymbolAddress((void**)&Sh[1], g_Sh1);
    cudaGetSymbolAddress((void**)&Sl[1], g_Sl1);
    cudaGetSymbolAddress((void**)&H,  g_H);
    cudaGetSymbolAddress((void**)&Y,  g_Y);

    const int SM_MAIN = 1024 + 2 * 98304;                 // 197632
    const int SM_MM   = (32 * 1024 + 16 * 32) * 4;        // 133120
    cudaFuncSetAttribute(k_gmain<0>, cudaFuncAttributeMaxDynamicSharedMemorySize, SM_MAIN);
    cudaFuncSetAttribute(k_gmain<1>, cudaFuncAttributeMaxDynamicSharedMemorySize, SM_MAIN);
    cudaFuncSetAttribute(k_loramm, cudaFuncAttributeMaxDynamicSharedMemorySize, SM_MM);

    // prep: M = lb@la into g_Y scratch, then W_eff = dequant(q,s) + M -> fp16 hi/lo
    k_loramm<<<6 * 64, 256, SM_MM>>>(lbw, la, Y);
    k_prepw<<<6 * DD * DD / 256, 256>>>(q, sc, Y);
    k_convert<<<MTOT * DD / 4 / 256, 256>>>(x);

    int p = 0;
    for (int blk = 0; blk < 3; ++blk) {
        int l0 = 2 * blk, l1 = 2 * blk + 1;
        k_gmain<0><<<dim3(4, MTOT / 128), 256, SM_MAIN>>>(
            Sh[p], Sl[p], Wh + (size_t)l0 * DD * DD, Wl + (size_t)l0 * DD * DD,
            bia + l0 * DD, nullptr, Y, nullptr, nullptr);
        k_lngelu<<<MTOT / 8, 256>>>(Y, gam + blk * DD, bet + blk * DD, Sh[p], Sl[p]);
        float* dst = (blk == 2) ? out : H;
        k_gmain<1><<<dim3(4, MTOT / 128), 256, SM_MAIN>>>(
            Sh[p], Sl[p], Wh + (size_t)l1 * DD * DD, Wl + (size_t)l1 * DD * DD,
            bia + l1 * DD, H, dst, Sh[p ^ 1], Sl[p ^ 1]);
        p ^= 1;
    }
}